// round 3
// baseline (speedup 1.0000x reference)
#include <cuda_runtime.h>

#define NN 100000
#define NE 3200000
#define FIN 512
#define HID 16
#define NC 64

// ---------------- scratch (static device globals; no allocation) ----------------
__device__ __align__(16) float g_bufA[NN * HID];
__device__ __align__(16) float g_bufB[NN * HID];
__device__ __align__(128) float g_row[NN * 32];   // per node: [hn[16] | h_raw[16]] (128B row)
__device__ int g_counts[NN + 1];
__device__ int g_rowptr[NN + 1];
__device__ int g_cursor[NN];
__device__ int g_colsrc[NE];

__constant__ __align__(16) float cW1[FIN * HID];
__constant__ __align__(16) float cB1[HID];
__constant__ __align__(16) float cW2[HID * NC];
__constant__ __align__(16) float cB2[NC];

// ---------------- small helpers ----------------
__device__ __forceinline__ float d4(float4 a, float4 b) {
    return a.x * b.x + a.y * b.y + a.z * b.z + a.w * b.w;
}
__device__ __forceinline__ float4 scl4(float4 a, float c) {
    return make_float4(a.x * c, a.y * c, a.z * c, a.w * c);
}
__device__ __forceinline__ unsigned long long pk2(float a, float b) {
    unsigned long long r;
    asm("mov.b64 %0, {%1, %2};" : "=l"(r) : "f"(a), "f"(b));
    return r;
}
__device__ __forceinline__ void upk2(unsigned long long v, float& a, float& b) {
    asm("mov.b64 {%0, %1}, %2;" : "=f"(a), "=f"(b) : "l"(v));
}
__device__ __forceinline__ void ffma2(unsigned long long& d, unsigned long long a, unsigned long long b) {
    asm("fma.rn.f32x2 %0, %1, %2, %0;" : "+l"(d) : "l"(a), "l"(b));
}

// ---------------- CSR build ----------------
__global__ void k_zero(int n) {
    int i = blockIdx.x * blockDim.x + threadIdx.x;
    if (i < n) g_counts[i] = 0;
}

__global__ void k_hist(const int* __restrict__ ei, int E) {
    int t = blockIdx.x * blockDim.x + threadIdx.x;
    int E4 = E >> 2;
    const int4* d4p = (const int4*)(ei + E);
    if (t < E4) {
        int4 d = __ldg(d4p + t);
        atomicAdd(&g_counts[d.x], 1);
        atomicAdd(&g_counts[d.y], 1);
        atomicAdd(&g_counts[d.z], 1);
        atomicAdd(&g_counts[d.w], 1);
    }
    if (t == 0) {
        for (int e = E4 * 4; e < E; e++) atomicAdd(&g_counts[ei[E + e]], 1);
    }
}

// single-block exclusive scan over g_counts[0..NN) -> g_rowptr, g_cursor
__global__ void k_scan(int n) {
    __shared__ int ssum[1024];
    const int CH = 128;
    int t = threadIdx.x;
    int base = t * CH;
    int s = 0;
    for (int i = 0; i < CH; i++) {
        int idx = base + i;
        if (idx < n) s += g_counts[idx];
    }
    ssum[t] = s;
    __syncthreads();
    for (int off = 1; off < 1024; off <<= 1) {
        int v = (t >= off) ? ssum[t - off] : 0;
        __syncthreads();
        ssum[t] += v;
        __syncthreads();
    }
    int excl = (t == 0) ? 0 : ssum[t - 1];
    for (int i = 0; i < CH; i++) {
        int idx = base + i;
        if (idx < n) {
            g_rowptr[idx] = excl;
            g_cursor[idx] = excl;
            excl += g_counts[idx];
        }
    }
    if (t == 1023) g_rowptr[n] = ssum[1023];
}

__global__ void k_scatter(const int* __restrict__ ei, int E) {
    int t = blockIdx.x * blockDim.x + threadIdx.x;
    int E4 = E >> 2;
    const int4* s4p = (const int4*)ei;
    const int4* d4p = (const int4*)(ei + E);
    if (t < E4) {
        int4 s = __ldg(s4p + t);
        int4 d = __ldg(d4p + t);
        int p;
        p = atomicAdd(&g_cursor[d.x], 1); g_colsrc[p] = s.x;
        p = atomicAdd(&g_cursor[d.y], 1); g_colsrc[p] = s.y;
        p = atomicAdd(&g_cursor[d.z], 1); g_colsrc[p] = s.z;
        p = atomicAdd(&g_cursor[d.w], 1); g_colsrc[p] = s.w;
    }
    if (t == 0) {
        for (int e = E4 * 4; e < E; e++) {
            int p = atomicAdd(&g_cursor[ei[E + e]], 1);
            g_colsrc[p] = ei[e];
        }
    }
}

// ---------------- h = relu(x @ W1 + b1): smem-staged coalesced x, thread-per-row ----------------
__global__ void __launch_bounds__(128) k_gemm1(const float4* __restrict__ x4, int n) {
    __shared__ float tile[128][132];   // stride 132 (odd in 16B units) -> conflict-free f4 LDS
    int t = threadIdx.x;               // 0..127
    int row0 = blockIdx.x * 128;

    unsigned long long acc[8];
#pragma unroll
    for (int j = 0; j < 8; j++) acc[j] = pk2(cB1[2 * j], cB1[2 * j + 1]);

#pragma unroll 1
    for (int kt = 0; kt < 4; kt++) {
        if (kt) __syncthreads();
        // coalesced load of 128 rows x 128 floats (k-chunk)
#pragma unroll
        for (int i = 0; i < 32; i++) {
            int fi = i * 128 + t;          // 0..4095 float4 slots
            int r = fi >> 5, c4 = fi & 31;
            int gr = row0 + r;
            float4 v = make_float4(0.f, 0.f, 0.f, 0.f);
            if (gr < n) v = __ldg(&x4[(long)gr * (FIN / 4) + kt * 32 + c4]);
            *(float4*)&tile[r][c4 * 4] = v;
        }
        __syncthreads();
        // compute: this thread's row from smem, weights from constant (uniform)
#pragma unroll 4
        for (int c4 = 0; c4 < 32; c4++) {
            float4 xv = *(const float4*)&tile[t][c4 * 4];
            int kb = kt * 128 + c4 * 4;
#pragma unroll
            for (int c = 0; c < 4; c++) {
                float xs = (c == 0) ? xv.x : (c == 1) ? xv.y : (c == 2) ? xv.z : xv.w;
                unsigned long long xx = pk2(xs, xs);
                const longlong2* w = (const longlong2*)&cW1[(kb + c) * HID];
#pragma unroll
                for (int j = 0; j < 4; j++) {
                    longlong2 wp = w[j];
                    ffma2(acc[2 * j], xx, (unsigned long long)wp.x);
                    ffma2(acc[2 * j + 1], xx, (unsigned long long)wp.y);
                }
            }
        }
    }

    int row = row0 + t;
    if (row >= n) return;
    float o[16];
#pragma unroll
    for (int j = 0; j < 8; j++) {
        float a, b;
        upk2(acc[j], a, b);
        o[2 * j] = fmaxf(a, 0.f);
        o[2 * j + 1] = fmaxf(b, 0.f);
    }
    float4* o4 = (float4*)&g_bufA[(long)row * HID];
#pragma unroll
    for (int j = 0; j < 4; j++)
        o4[j] = make_float4(o[4 * j], o[4 * j + 1], o[4 * j + 2], o[4 * j + 3]);
}

// ---------------- build per-node 128B row: [hn | h_raw] ----------------
__global__ void k_norm(int srcSel, int n) {
    int i = blockIdx.x * blockDim.x + threadIdx.x;
    if (i >= n) return;
    const float4* h4 = (const float4*)(srcSel ? g_bufB : g_bufA);
    float4 v0 = h4[i * 4 + 0], v1 = h4[i * 4 + 1], v2 = h4[i * 4 + 2], v3 = h4[i * 4 + 3];
    float ss = d4(v0, v0) + d4(v1, v1) + d4(v2, v2) + d4(v3, v3);
    float inv = 1.0f / fmaxf(sqrtf(ss), 1e-12f);
    float4* r4 = (float4*)&g_row[(long)i * 32];
    r4[0] = scl4(v0, inv);
    r4[1] = scl4(v1, inv);
    r4[2] = scl4(v2, inv);
    r4[3] = scl4(v3, inv);
    r4[4] = v0; r4[5] = v1; r4[6] = v2; r4[7] = v3;
}

// ---------------- AGNN layer: warp/node, 8 lanes/edge, NO max-subtraction ----------------
// logits = beta*cos are bounded by |beta| (cos in [-1,1]); exp() cannot overflow,
// so softmax is computed directly: s = sum exp(l), a = sum exp(l)*x.
// This removes the serial online-softmax chain -> fully pipelined gathers.
__global__ void k_agnn(const float* __restrict__ beta_p, int outSel, int n) {
    int lane = threadIdx.x & 31;
    int warp = threadIdx.x >> 5;
    int node = blockIdx.x * 8 + warp;
    if (node >= n) return;               // whole warp exits together
    int sub = lane & 7;                   // 16B chunk of the 128B row
    int slot = lane >> 3;                 // 4 concurrent edges
    float beta = __ldg(beta_p);
    const float4* row4 = (const float4*)g_row;

    float4 dv = row4[(long)node * 8 + sub];   // sub<4: hn chunk; sub>=4: raw chunk

    // self-loop cosine = hn.hn
    float cs = (sub < 4) ? d4(dv, dv) : 0.f;
    cs += __shfl_xor_sync(0xffffffffu, cs, 1, 8);
    cs += __shfl_xor_sync(0xffffffffu, cs, 2, 8);
    cs += __shfl_xor_sync(0xffffffffu, cs, 4, 8);

    float s = 0.f;
    float4 a = make_float4(0.f, 0.f, 0.f, 0.f);

    int e0 = g_rowptr[node];
    int cnt = g_rowptr[node + 1] - e0;
    for (int base = 0; base < cnt; base += 4) {
        int idx = base + slot;
        bool v = idx < cnt;
        int sn = v ? __ldg(&g_colsrc[e0 + idx]) : node;
        float4 sv = __ldg(&row4[(long)sn * 8 + sub]);   // one 128B line per edge
        float pp = (sub < 4) ? d4(dv, sv) : 0.f;
        pp += __shfl_xor_sync(0xffffffffu, pp, 1, 8);
        pp += __shfl_xor_sync(0xffffffffu, pp, 2, 8);
        pp += __shfl_xor_sync(0xffffffffu, pp, 4, 8);
        float p = v ? __expf(beta * pp) : 0.f;
        s += p;
        a.x += p * sv.x; a.y += p * sv.y; a.z += p * sv.z; a.w += p * sv.w;
    }

    // combine the 4 slot partial sums (plain sums now)
#pragma unroll
    for (int off = 8; off <= 16; off <<= 1) {
        s += __shfl_xor_sync(0xffffffffu, s, off);
        a.x += __shfl_xor_sync(0xffffffffu, a.x, off);
        a.y += __shfl_xor_sync(0xffffffffu, a.y, off);
        a.z += __shfl_xor_sync(0xffffffffu, a.z, off);
        a.w += __shfl_xor_sync(0xffffffffu, a.w, off);
    }

    // add implicit self-loop once
    float ps = __expf(beta * cs);
    s += ps;
    a.x += ps * dv.x; a.y += ps * dv.y; a.z += ps * dv.z; a.w += ps * dv.w;

    if (sub >= 4) {
        float4* out4 = (float4*)(outSel ? g_bufB : g_bufA);
        out4[(long)node * 4 + (sub - 4)] = scl4(a, 1.0f / s);
    }
}

// ---------------- out = log_softmax(h @ W2 + b2), warp-per-row ----------------
__global__ void k_gemm2(int srcSel, float* __restrict__ out, int n) {
    __shared__ float sW[HID * NC];
    __shared__ float sB[NC];
    for (int i = threadIdx.x; i < HID * NC; i += blockDim.x) sW[i] = cW2[i];
    if (threadIdx.x < NC) sB[threadIdx.x] = cB2[threadIdx.x];
    __syncthreads();

    int warp = threadIdx.x >> 5, lane = threadIdx.x & 31;
    int row = blockIdx.x * (blockDim.x >> 5) + warp;
    if (row >= n) return;

    const float* h = srcSel ? g_bufB : g_bufA;
    float hv = (lane < HID) ? h[(long)row * HID + lane] : 0.f;
    float z0 = sB[lane], z1 = sB[lane + 32];
#pragma unroll
    for (int k = 0; k < HID; k++) {
        float hk = __shfl_sync(0xffffffffu, hv, k);
        z0 += hk * sW[k * NC + lane];
        z1 += hk * sW[k * NC + 32 + lane];
    }
    float mx = fmaxf(z0, z1);
#pragma unroll
    for (int off = 16; off > 0; off >>= 1) mx = fmaxf(mx, __shfl_xor_sync(0xffffffffu, mx, off));
    float p = __expf(z0 - mx) + __expf(z1 - mx);
#pragma unroll
    for (int off = 16; off > 0; off >>= 1) p += __shfl_xor_sync(0xffffffffu, p, off);
    float lse = mx + __logf(p);
    out[(long)row * NC + lane] = z0 - lse;
    out[(long)row * NC + 32 + lane] = z1 - lse;
}

// ---------------- launch ----------------
extern "C" void kernel_launch(void* const* d_in, const int* in_sizes, int n_in,
                              void* d_out, int out_size) {
    const float* x = (const float*)d_in[0];
    const int* ei = (const int*)d_in[1];
    const float* W1 = (const float*)d_in[2];
    const float* b1 = (const float*)d_in[3];
    const float* W2 = (const float*)d_in[4];
    const float* b2 = (const float*)d_in[5];
    const float* beta1 = (const float*)d_in[6];
    const float* beta2 = (const float*)d_in[7];
    float* out = (float*)d_out;

    int N = in_sizes[0] / FIN;
    int E = in_sizes[1] / 2;

    cudaMemcpyToSymbolAsync(cW1, W1, FIN * HID * sizeof(float), 0, cudaMemcpyDeviceToDevice, 0);
    cudaMemcpyToSymbolAsync(cB1, b1, HID * sizeof(float), 0, cudaMemcpyDeviceToDevice, 0);
    cudaMemcpyToSymbolAsync(cW2, W2, HID * NC * sizeof(float), 0, cudaMemcpyDeviceToDevice, 0);
    cudaMemcpyToSymbolAsync(cB2, b2, NC * sizeof(float), 0, cudaMemcpyDeviceToDevice, 0);

    // CSR build; gemm1 placed 4th so the profiler's fixed slot captures it
    k_zero<<<(N + 255) / 256, 256>>>(N);
    k_hist<<<(E / 4 + 255) / 256, 256>>>(ei, E);
    k_scan<<<1, 1024>>>(N);
    k_gemm1<<<(N + 127) / 128, 128>>>((const float4*)x, N);
    k_scatter<<<(E / 4 + 255) / 256, 256>>>(ei, E);

    // layer 1: bufA -> bufB
    k_norm<<<(N + 255) / 256, 256>>>(0, N);
    k_agnn<<<(N + 7) / 8, 256>>>(beta1, 1, N);

    // layer 2: bufB -> bufA
    k_norm<<<(N + 255) / 256, 256>>>(1, N);
    k_agnn<<<(N + 7) / 8, 256>>>(beta2, 0, N);

    // MLP out + log_softmax
    k_gemm2<<<(N + 7) / 8, 256>>>(0, out, N);
}

// round 4
// speedup vs baseline: 1.0970x; 1.0970x over previous
#include <cuda_runtime.h>

#define NN 100000
#define NE 3200000
#define FIN 512
#define HID 16
#define NC 64

// ---------------- scratch (static device globals; no allocation) ----------------
__device__ __align__(16) float g_bufA[NN * HID];
__device__ __align__(16) float g_bufB[NN * HID];
__device__ __align__(128) float g_row[NN * 32];   // per node: [hn[16] | h_raw[16]] (128B row)
__device__ int g_counts[NN + 1];
__device__ int g_rowptr[NN + 1];
__device__ int g_cursor[NN];
__device__ int g_colsrc[NE];

__constant__ __align__(16) float cW2[HID * NC];
__constant__ __align__(16) float cB2[NC];

// ---------------- small helpers ----------------
__device__ __forceinline__ float d4(float4 a, float4 b) {
    return a.x * b.x + a.y * b.y + a.z * b.z + a.w * b.w;
}
__device__ __forceinline__ float4 scl4(float4 a, float c) {
    return make_float4(a.x * c, a.y * c, a.z * c, a.w * c);
}
__device__ __forceinline__ unsigned long long pk2(float a, float b) {
    unsigned long long r;
    asm("mov.b64 %0, {%1, %2};" : "=l"(r) : "f"(a), "f"(b));
    return r;
}
__device__ __forceinline__ void upk2(unsigned long long v, float& a, float& b) {
    asm("mov.b64 {%0, %1}, %2;" : "=f"(a), "=f"(b) : "l"(v));
}
__device__ __forceinline__ void ffma2(unsigned long long& d, unsigned long long a, unsigned long long b) {
    asm("fma.rn.f32x2 %0, %1, %2, %0;" : "+l"(d) : "l"(a), "l"(b));
}

// ---------------- CSR build ----------------
__global__ void k_zero(int n) {
    int i = blockIdx.x * blockDim.x + threadIdx.x;
    if (i < n) g_counts[i] = 0;
}

__global__ void k_hist(const int* __restrict__ ei, int E) {
    int t = blockIdx.x * blockDim.x + threadIdx.x;
    int E4 = E >> 2;
    const int4* d4p = (const int4*)(ei + E);
    if (t < E4) {
        int4 d = __ldg(d4p + t);
        atomicAdd(&g_counts[d.x], 1);
        atomicAdd(&g_counts[d.y], 1);
        atomicAdd(&g_counts[d.z], 1);
        atomicAdd(&g_counts[d.w], 1);
    }
    if (t == 0) {
        for (int e = E4 * 4; e < E; e++) atomicAdd(&g_counts[ei[E + e]], 1);
    }
}

__global__ void k_scan(int n) {
    __shared__ int ssum[1024];
    const int CH = 128;
    int t = threadIdx.x;
    int base = t * CH;
    int s = 0;
    for (int i = 0; i < CH; i++) {
        int idx = base + i;
        if (idx < n) s += g_counts[idx];
    }
    ssum[t] = s;
    __syncthreads();
    for (int off = 1; off < 1024; off <<= 1) {
        int v = (t >= off) ? ssum[t - off] : 0;
        __syncthreads();
        ssum[t] += v;
        __syncthreads();
    }
    int excl = (t == 0) ? 0 : ssum[t - 1];
    for (int i = 0; i < CH; i++) {
        int idx = base + i;
        if (idx < n) {
            g_rowptr[idx] = excl;
            g_cursor[idx] = excl;
            excl += g_counts[idx];
        }
    }
    if (t == 1023) g_rowptr[n] = ssum[1023];
}

__global__ void k_scatter(const int* __restrict__ ei, int E) {
    int t = blockIdx.x * blockDim.x + threadIdx.x;
    int E4 = E >> 2;
    const int4* s4p = (const int4*)ei;
    const int4* d4p = (const int4*)(ei + E);
    if (t < E4) {
        int4 s = __ldg(s4p + t);
        int4 d = __ldg(d4p + t);
        int p;
        p = atomicAdd(&g_cursor[d.x], 1); g_colsrc[p] = s.x;
        p = atomicAdd(&g_cursor[d.y], 1); g_colsrc[p] = s.y;
        p = atomicAdd(&g_cursor[d.z], 1); g_colsrc[p] = s.z;
        p = atomicAdd(&g_cursor[d.w], 1); g_colsrc[p] = s.w;
    }
    if (t == 0) {
        for (int e = E4 * 4; e < E; e++) {
            int p = atomicAdd(&g_cursor[ei[E + e]], 1);
            g_colsrc[p] = ei[e];
        }
    }
}

// ---------------- fused: h = relu(x@W1+b1); L2-normalize; build g_row ----------------
// Weights in SMEM (uniform LDS.128 broadcast), x staged via SMEM for coalescing.
#define G1_SMEM_BYTES ((FIN * HID + 128 * 68) * 4)
__global__ void __launch_bounds__(128) k_gemm1(const float4* __restrict__ x4,
                                               const float* __restrict__ W1,
                                               const float* __restrict__ b1, int n) {
    extern __shared__ float dsm[];
    float* sW = dsm;                      // 8192 floats = 32KB
    float* tile = dsm + FIN * HID;        // [128][68], stride 68 (68%32==4 -> conflict-free f4)
    int t = threadIdx.x;                  // 0..127
    int row0 = blockIdx.x * 128;

    // load W1 into smem (coalesced)
    const float4* w4g = (const float4*)W1;
    float4* w4s = (float4*)sW;
#pragma unroll
    for (int i = 0; i < 16; i++) w4s[i * 128 + t] = __ldg(&w4g[i * 128 + t]);

    unsigned long long acc[8];
#pragma unroll
    for (int j = 0; j < 8; j++) acc[j] = pk2(__ldg(&b1[2 * j]), __ldg(&b1[2 * j + 1]));

#pragma unroll 1
    for (int kt = 0; kt < 8; kt++) {
        __syncthreads();
        // coalesced stage of 128 rows x 64 floats (k-chunk kt)
#pragma unroll
        for (int i = 0; i < 16; i++) {
            int fi = i * 128 + t;
            int r = fi >> 4, c4 = fi & 15;
            int gr = row0 + r;
            float4 v = make_float4(0.f, 0.f, 0.f, 0.f);
            if (gr < n) v = __ldg(&x4[(long)gr * (FIN / 4) + kt * 16 + c4]);
            *(float4*)&tile[r * 68 + c4 * 4] = v;
        }
        __syncthreads();
#pragma unroll 2
        for (int c4 = 0; c4 < 16; c4++) {
            float4 xv = *(const float4*)&tile[t * 68 + c4 * 4];
#pragma unroll
            for (int c = 0; c < 4; c++) {
                float xs = (c == 0) ? xv.x : (c == 1) ? xv.y : (c == 2) ? xv.z : xv.w;
                unsigned long long xx = pk2(xs, xs);
                const ulonglong2* w = (const ulonglong2*)&sW[(kt * 64 + c4 * 4 + c) * HID];
                ulonglong2 wa = w[0], wb = w[1];   // 2x LDS.128 uniform broadcast
                ffma2(acc[0], xx, wa.x);
                ffma2(acc[1], xx, wa.y);
                ffma2(acc[2], xx, wb.x);
                ffma2(acc[3], xx, wb.y);
                ulonglong2 wc = w[2], wd = w[3];
                ffma2(acc[4], xx, wc.x);
                ffma2(acc[5], xx, wc.y);
                ffma2(acc[6], xx, wd.x);
                ffma2(acc[7], xx, wd.y);
            }
        }
    }

    int row = row0 + t;
    if (row >= n) return;
    float o[16];
    float ss = 0.f;
#pragma unroll
    for (int j = 0; j < 8; j++) {
        float a, b;
        upk2(acc[j], a, b);
        a = fmaxf(a, 0.f);
        b = fmaxf(b, 0.f);
        o[2 * j] = a; o[2 * j + 1] = b;
        ss += a * a + b * b;
    }
    float inv = 1.0f / fmaxf(sqrtf(ss), 1e-12f);
    float4* r4 = (float4*)&g_row[(long)row * 32];
#pragma unroll
    for (int j = 0; j < 4; j++) {
        float4 raw = make_float4(o[4 * j], o[4 * j + 1], o[4 * j + 2], o[4 * j + 3]);
        r4[j] = scl4(raw, inv);
        r4[4 + j] = raw;
    }
}

// ---------------- build per-node 128B row from bufB (between layers) ----------------
__global__ void k_norm(int n) {
    int i = blockIdx.x * blockDim.x + threadIdx.x;
    if (i >= n) return;
    const float4* h4 = (const float4*)g_bufB;
    float4 v0 = h4[i * 4 + 0], v1 = h4[i * 4 + 1], v2 = h4[i * 4 + 2], v3 = h4[i * 4 + 3];
    float ss = d4(v0, v0) + d4(v1, v1) + d4(v2, v2) + d4(v3, v3);
    float inv = 1.0f / fmaxf(sqrtf(ss), 1e-12f);
    float4* r4 = (float4*)&g_row[(long)i * 32];
    r4[0] = scl4(v0, inv);
    r4[1] = scl4(v1, inv);
    r4[2] = scl4(v2, inv);
    r4[3] = scl4(v3, inv);
    r4[4] = v0; r4[5] = v1; r4[6] = v2; r4[7] = v3;
}

// ---------------- AGNN layer: warp/node, 8 lanes/edge, prefetched gathers ----------------
// logits bounded by |beta| (cos in [-1,1]) -> direct softmax, no max subtraction.
__global__ void k_agnn(const float* __restrict__ beta_p, int outSel, int n) {
    int lane = threadIdx.x & 31;
    int warp = threadIdx.x >> 5;
    int node = blockIdx.x * 8 + warp;
    if (node >= n) return;
    int sub = lane & 7;
    int slot = lane >> 3;
    float beta = __ldg(beta_p);
    const float4* row4 = (const float4*)g_row;

    float4 dv = row4[(long)node * 8 + sub];

    float cs = (sub < 4) ? d4(dv, dv) : 0.f;
    cs += __shfl_xor_sync(0xffffffffu, cs, 1, 8);
    cs += __shfl_xor_sync(0xffffffffu, cs, 2, 8);
    cs += __shfl_xor_sync(0xffffffffu, cs, 4, 8);

    int e0 = g_rowptr[node];
    int cnt = g_rowptr[node + 1] - e0;

    float s = 0.f;
    float4 a = make_float4(0.f, 0.f, 0.f, 0.f);

    // prologue: load edge (slot)
    bool v = slot < cnt;
    int sn = v ? __ldg(&g_colsrc[e0 + slot]) : node;
    float4 sv = __ldg(&row4[(long)sn * 8 + sub]);

    for (int base = 0; base < cnt; base += 4) {
        // prefetch next 4 edges before the dependent math chain
        int nidx = base + 4 + slot;
        bool nv = nidx < cnt;
        int nsn = nv ? __ldg(&g_colsrc[e0 + nidx]) : node;
        float4 nsv = __ldg(&row4[(long)nsn * 8 + sub]);

        float pp = (sub < 4) ? d4(dv, sv) : 0.f;
        pp += __shfl_xor_sync(0xffffffffu, pp, 1, 8);
        pp += __shfl_xor_sync(0xffffffffu, pp, 2, 8);
        pp += __shfl_xor_sync(0xffffffffu, pp, 4, 8);
        float p = v ? __expf(beta * pp) : 0.f;
        s += p;
        a.x += p * sv.x; a.y += p * sv.y; a.z += p * sv.z; a.w += p * sv.w;

        v = nv; sv = nsv;
    }

    // combine the 4 slot partials
#pragma unroll
    for (int off = 8; off <= 16; off <<= 1) {
        s += __shfl_xor_sync(0xffffffffu, s, off);
        a.x += __shfl_xor_sync(0xffffffffu, a.x, off);
        a.y += __shfl_xor_sync(0xffffffffu, a.y, off);
        a.z += __shfl_xor_sync(0xffffffffu, a.z, off);
        a.w += __shfl_xor_sync(0xffffffffu, a.w, off);
    }

    // implicit self-loop
    float ps = __expf(beta * cs);
    s += ps;
    a.x += ps * dv.x; a.y += ps * dv.y; a.z += ps * dv.z; a.w += ps * dv.w;

    if (sub >= 4) {
        float4* out4 = (float4*)(outSel ? g_bufB : g_bufA);
        out4[(long)node * 4 + (sub - 4)] = scl4(a, 1.0f / s);
    }
}

// ---------------- out = log_softmax(h @ W2 + b2), warp-per-row ----------------
__global__ void k_gemm2(float* __restrict__ out, int n) {
    __shared__ float sW[HID * NC];
    __shared__ float sB[NC];
    for (int i = threadIdx.x; i < HID * NC; i += blockDim.x) sW[i] = cW2[i];
    if (threadIdx.x < NC) sB[threadIdx.x] = cB2[threadIdx.x];
    __syncthreads();

    int warp = threadIdx.x >> 5, lane = threadIdx.x & 31;
    int row = blockIdx.x * (blockDim.x >> 5) + warp;
    if (row >= n) return;

    const float* h = g_bufA;
    float hv = (lane < HID) ? h[(long)row * HID + lane] : 0.f;
    float z0 = sB[lane], z1 = sB[lane + 32];
#pragma unroll
    for (int k = 0; k < HID; k++) {
        float hk = __shfl_sync(0xffffffffu, hv, k);
        z0 += hk * sW[k * NC + lane];
        z1 += hk * sW[k * NC + 32 + lane];
    }
    float mx = fmaxf(z0, z1);
#pragma unroll
    for (int off = 16; off > 0; off >>= 1) mx = fmaxf(mx, __shfl_xor_sync(0xffffffffu, mx, off));
    float p = __expf(z0 - mx) + __expf(z1 - mx);
#pragma unroll
    for (int off = 16; off > 0; off >>= 1) p += __shfl_xor_sync(0xffffffffu, p, off);
    float lse = mx + __logf(p);
    out[(long)row * NC + lane] = z0 - lse;
    out[(long)row * NC + 32 + lane] = z1 - lse;
}

// ---------------- launch ----------------
extern "C" void kernel_launch(void* const* d_in, const int* in_sizes, int n_in,
                              void* d_out, int out_size) {
    const float* x = (const float*)d_in[0];
    const int* ei = (const int*)d_in[1];
    const float* W1 = (const float*)d_in[2];
    const float* b1 = (const float*)d_in[3];
    const float* W2 = (const float*)d_in[4];
    const float* b2 = (const float*)d_in[5];
    const float* beta1 = (const float*)d_in[6];
    const float* beta2 = (const float*)d_in[7];
    float* out = (float*)d_out;

    int N = in_sizes[0] / FIN;
    int E = in_sizes[1] / 2;

    cudaMemcpyToSymbolAsync(cW2, W2, HID * NC * sizeof(float), 0, cudaMemcpyDeviceToDevice, 0);
    cudaMemcpyToSymbolAsync(cB2, b2, NC * sizeof(float), 0, cudaMemcpyDeviceToDevice, 0);

    static int smemSet = 0;
    if (!smemSet) {
        cudaFuncSetAttribute(k_gemm1, cudaFuncAttributeMaxDynamicSharedMemorySize, G1_SMEM_BYTES);
        smemSet = 1;
    }

    // CSR build; gemm1 kept in profiler slot 4
    k_zero<<<(N + 255) / 256, 256>>>(N);
    k_hist<<<(E / 4 + 255) / 256, 256>>>(ei, E);
    k_scan<<<1, 1024>>>(N);
    k_gemm1<<<(N + 127) / 128, 128, G1_SMEM_BYTES>>>((const float4*)x, W1, b1, N);
    k_scatter<<<(E / 4 + 255) / 256, 256>>>(ei, E);

    // layer 1: g_row -> bufB
    k_agnn<<<(N + 7) / 8, 256>>>(beta1, 1, N);

    // layer 2: bufB -> g_row -> bufA
    k_norm<<<(N + 255) / 256, 256>>>(N);
    k_agnn<<<(N + 7) / 8, 256>>>(beta2, 0, N);

    // MLP out + log_softmax
    k_gemm2<<<(N + 7) / 8, 256>>>(out, N);
}

// round 5
// speedup vs baseline: 1.8173x; 1.6566x over previous
#include <cuda_runtime.h>

#define NN 100000
#define NE 3200000
#define FIN 512
#define HID 16
#define NC 64

// ---------------- scratch (static device globals; no allocation) ----------------
__device__ __align__(16) float g_bufA[NN * HID];
__device__ __align__(16) float g_bufB[NN * HID];
__device__ __align__(128) float g_row[NN * 32];   // per node: [hn[16] | h_raw[16]] (128B row)
__device__ int g_counts[NN + 1];
__device__ int g_rowptr[NN + 1];
__device__ int g_cursor[NN];
__device__ int g_colsrc[NE];
__device__ int g_bsum[128];

__constant__ __align__(16) float cW2[HID * NC];
__constant__ __align__(16) float cB2[NC];

// ---------------- small helpers ----------------
__device__ __forceinline__ float d4(float4 a, float4 b) {
    return a.x * b.x + a.y * b.y + a.z * b.z + a.w * b.w;
}
__device__ __forceinline__ float4 scl4(float4 a, float c) {
    return make_float4(a.x * c, a.y * c, a.z * c, a.w * c);
}
__device__ __forceinline__ unsigned long long pk2(float a, float b) {
    unsigned long long r;
    asm("mov.b64 %0, {%1, %2};" : "=l"(r) : "f"(a), "f"(b));
    return r;
}
__device__ __forceinline__ void upk2(unsigned long long v, float& a, float& b) {
    asm("mov.b64 {%0, %1}, %2;" : "=f"(a), "=f"(b) : "l"(v));
}
__device__ __forceinline__ void ffma2(unsigned long long& d, unsigned long long a, unsigned long long b) {
    asm("fma.rn.f32x2 %0, %1, %2, %0;" : "+l"(d) : "l"(a), "l"(b));
}

// ---------------- CSR build ----------------
__global__ void k_zero(int n) {
    int i = blockIdx.x * blockDim.x + threadIdx.x;
    if (i < n) g_counts[i] = 0;
}

__global__ void k_hist(const int* __restrict__ ei, int E) {
    int t = blockIdx.x * blockDim.x + threadIdx.x;
    int E4 = E >> 2;
    const int4* d4p = (const int4*)(ei + E);
    if (t < E4) {
        int4 d = __ldg(d4p + t);
        atomicAdd(&g_counts[d.x], 1);
        atomicAdd(&g_counts[d.y], 1);
        atomicAdd(&g_counts[d.z], 1);
        atomicAdd(&g_counts[d.w], 1);
    }
    if (t == 0) {
        for (int e = E4 * 4; e < E; e++) atomicAdd(&g_counts[ei[E + e]], 1);
    }
}

// ---- pass 1: per-block (1024 elems) sums, coalesced ----
__global__ void __launch_bounds__(1024) k_presum(int n) {
    int t = threadIdx.x, lane = t & 31, w = t >> 5;
    int i = blockIdx.x * 1024 + t;
    int v = (i < n) ? g_counts[i] : 0;
#pragma unroll
    for (int off = 16; off > 0; off >>= 1) v += __shfl_xor_sync(0xffffffffu, v, off);
    __shared__ int ws[32];
    if (lane == 0) ws[w] = v;
    __syncthreads();
    if (t < 32) {
        int s = ws[t];
#pragma unroll
        for (int off = 16; off > 0; off >>= 1) s += __shfl_xor_sync(0xffffffffu, s, off);
        if (t == 0) g_bsum[blockIdx.x] = s;
    }
}

// ---- pass 2: block exclusive scan + global offset, coalesced writes ----
__global__ void __launch_bounds__(1024) k_scanout(int n) {
    int t = threadIdx.x, lane = t & 31, w = t >> 5;
    __shared__ int wsum[32];
    __shared__ int s_boff;

    if (w == 0) {
        int s = 0;
#pragma unroll
        for (int k2 = 0; k2 < 4; k2++) {
            int j = lane + 32 * k2;
            if (j < blockIdx.x) s += g_bsum[j];
        }
#pragma unroll
        for (int off = 16; off > 0; off >>= 1) s += __shfl_xor_sync(0xffffffffu, s, off);
        if (lane == 0) s_boff = s;
    }

    int i = blockIdx.x * 1024 + t;
    int v = (i < n) ? g_counts[i] : 0;
    int x = v;
#pragma unroll
    for (int off = 1; off < 32; off <<= 1) {
        int y = __shfl_up_sync(0xffffffffu, x, off);
        if (lane >= off) x += y;
    }
    if (lane == 31) wsum[w] = x;
    __syncthreads();
    if (w == 0) {
        int y = wsum[lane];
        int inc = y;
#pragma unroll
        for (int off = 1; off < 32; off <<= 1) {
            int z = __shfl_up_sync(0xffffffffu, inc, off);
            if (lane >= off) inc += z;
        }
        wsum[lane] = inc - y;   // exclusive
    }
    __syncthreads();
    int excl = s_boff + wsum[w] + (x - v);
    if (i <= n) {
        g_rowptr[i] = excl;
        if (i < n) g_cursor[i] = excl;
    }
}

__global__ void k_scatter(const int* __restrict__ ei, int E) {
    int t = blockIdx.x * blockDim.x + threadIdx.x;
    int E4 = E >> 2;
    const int4* s4p = (const int4*)ei;
    const int4* d4p = (const int4*)(ei + E);
    if (t < E4) {
        int4 s = __ldg(s4p + t);
        int4 d = __ldg(d4p + t);
        int p;
        p = atomicAdd(&g_cursor[d.x], 1); g_colsrc[p] = s.x;
        p = atomicAdd(&g_cursor[d.y], 1); g_colsrc[p] = s.y;
        p = atomicAdd(&g_cursor[d.z], 1); g_colsrc[p] = s.z;
        p = atomicAdd(&g_cursor[d.w], 1); g_colsrc[p] = s.w;
    }
    if (t == 0) {
        for (int e = E4 * 4; e < E; e++) {
            int p = atomicAdd(&g_cursor[ei[E + e]], 1);
            g_colsrc[p] = ei[e];
        }
    }
}

// ---------------- fused: h = relu(x@W1+b1); L2-normalize; build g_row ----------------
// 128 threads, 2 rows/thread (256 rows/block), 16-float k-chunks. W1 in smem.
#define G1_SMEM_BYTES ((FIN * HID + 256 * 20) * 4)
__global__ void __launch_bounds__(128) k_gemm1(const float4* __restrict__ x4,
                                               const float* __restrict__ W1,
                                               const float* __restrict__ b1, int n) {
    extern __shared__ float dsm[];
    float* sW = dsm;                      // 8192 floats = 32KB
    float* tile = dsm + FIN * HID;        // [256][20] floats (80B row stride, f4-aligned)
    int t = threadIdx.x;
    int row0 = blockIdx.x * 256;

    // load W1 into smem (coalesced)
    const float4* w4g = (const float4*)W1;
    float4* w4s = (float4*)sW;
#pragma unroll
    for (int i = 0; i < 16; i++) w4s[i * 128 + t] = __ldg(&w4g[i * 128 + t]);

    unsigned long long accA[8], accB[8];
#pragma unroll
    for (int j = 0; j < 8; j++) {
        unsigned long long b = pk2(__ldg(&b1[2 * j]), __ldg(&b1[2 * j + 1]));
        accA[j] = b; accB[j] = b;
    }

#pragma unroll 1
    for (int kt = 0; kt < 32; kt++) {
        __syncthreads();
        // stage 256 rows x 16 floats (k-chunk kt), coalesced
#pragma unroll
        for (int i = 0; i < 8; i++) {
            int fi = i * 128 + t;          // 1024 float4 slots
            int r = fi >> 2, c4 = fi & 3;
            int gr = row0 + r;
            float4 v = make_float4(0.f, 0.f, 0.f, 0.f);
            if (gr < n) v = __ldg(&x4[(long)gr * (FIN / 4) + kt * 4 + c4]);
            *(float4*)&tile[r * 20 + c4 * 4] = v;
        }
        __syncthreads();
#pragma unroll
        for (int c4 = 0; c4 < 4; c4++) {
            float4 xa = *(const float4*)&tile[t * 20 + c4 * 4];
            float4 xb = *(const float4*)&tile[(t + 128) * 20 + c4 * 4];
#pragma unroll
            for (int c = 0; c < 4; c++) {
                float xsa = (c == 0) ? xa.x : (c == 1) ? xa.y : (c == 2) ? xa.z : xa.w;
                float xsb = (c == 0) ? xb.x : (c == 1) ? xb.y : (c == 2) ? xb.z : xb.w;
                unsigned long long xxa = pk2(xsa, xsa);
                unsigned long long xxb = pk2(xsb, xsb);
                const ulonglong2* w = (const ulonglong2*)&sW[(kt * 16 + c4 * 4 + c) * HID];
                ulonglong2 wa = w[0], wb = w[1], wc = w[2], wd = w[3];
                ffma2(accA[0], xxa, wa.x); ffma2(accA[1], xxa, wa.y);
                ffma2(accA[2], xxa, wb.x); ffma2(accA[3], xxa, wb.y);
                ffma2(accA[4], xxa, wc.x); ffma2(accA[5], xxa, wc.y);
                ffma2(accA[6], xxa, wd.x); ffma2(accA[7], xxa, wd.y);
                ffma2(accB[0], xxb, wa.x); ffma2(accB[1], xxb, wa.y);
                ffma2(accB[2], xxb, wb.x); ffma2(accB[3], xxb, wb.y);
                ffma2(accB[4], xxb, wc.x); ffma2(accB[5], xxb, wc.y);
                ffma2(accB[6], xxb, wd.x); ffma2(accB[7], xxb, wd.y);
            }
        }
    }

#pragma unroll
    for (int half = 0; half < 2; half++) {
        int row = row0 + t + half * 128;
        if (row >= n) continue;
        unsigned long long* acc = half ? accB : accA;
        float o[16];
        float ss = 0.f;
#pragma unroll
        for (int j = 0; j < 8; j++) {
            float a, b;
            upk2(acc[j], a, b);
            a = fmaxf(a, 0.f);
            b = fmaxf(b, 0.f);
            o[2 * j] = a; o[2 * j + 1] = b;
            ss += a * a + b * b;
        }
        float inv = 1.0f / fmaxf(sqrtf(ss), 1e-12f);
        float4* r4 = (float4*)&g_row[(long)row * 32];
#pragma unroll
        for (int j = 0; j < 4; j++) {
            float4 raw = make_float4(o[4 * j], o[4 * j + 1], o[4 * j + 2], o[4 * j + 3]);
            r4[j] = scl4(raw, inv);
            r4[4 + j] = raw;
        }
    }
}

// ---------------- build per-node 128B row from bufB (between layers) ----------------
__global__ void k_norm(int n) {
    int i = blockIdx.x * blockDim.x + threadIdx.x;
    if (i >= n) return;
    const float4* h4 = (const float4*)g_bufB;
    float4 v0 = h4[i * 4 + 0], v1 = h4[i * 4 + 1], v2 = h4[i * 4 + 2], v3 = h4[i * 4 + 3];
    float ss = d4(v0, v0) + d4(v1, v1) + d4(v2, v2) + d4(v3, v3);
    float inv = 1.0f / fmaxf(sqrtf(ss), 1e-12f);
    float4* r4 = (float4*)&g_row[(long)i * 32];
    r4[0] = scl4(v0, inv);
    r4[1] = scl4(v1, inv);
    r4[2] = scl4(v2, inv);
    r4[3] = scl4(v3, inv);
    r4[4] = v0; r4[5] = v1; r4[6] = v2; r4[7] = v3;
}

// ---------------- AGNN layer: warp/node, 8 lanes/edge, prefetched gathers ----------------
__global__ void k_agnn(const float* __restrict__ beta_p, int outSel, int n) {
    int lane = threadIdx.x & 31;
    int warp = threadIdx.x >> 5;
    int node = blockIdx.x * 8 + warp;
    if (node >= n) return;
    int sub = lane & 7;
    int slot = lane >> 3;
    float beta = __ldg(beta_p);
    const float4* row4 = (const float4*)g_row;

    float4 dv = row4[(long)node * 8 + sub];

    float cs = (sub < 4) ? d4(dv, dv) : 0.f;
    cs += __shfl_xor_sync(0xffffffffu, cs, 1, 8);
    cs += __shfl_xor_sync(0xffffffffu, cs, 2, 8);
    cs += __shfl_xor_sync(0xffffffffu, cs, 4, 8);

    int e0 = g_rowptr[node];
    int cnt = g_rowptr[node + 1] - e0;

    float s = 0.f;
    float4 a = make_float4(0.f, 0.f, 0.f, 0.f);

    bool v = slot < cnt;
    int sn = v ? __ldg(&g_colsrc[e0 + slot]) : node;
    float4 sv = __ldg(&row4[(long)sn * 8 + sub]);

    for (int base = 0; base < cnt; base += 4) {
        int nidx = base + 4 + slot;
        bool nv = nidx < cnt;
        int nsn = nv ? __ldg(&g_colsrc[e0 + nidx]) : node;
        float4 nsv = __ldg(&row4[(long)nsn * 8 + sub]);

        float pp = (sub < 4) ? d4(dv, sv) : 0.f;
        pp += __shfl_xor_sync(0xffffffffu, pp, 1, 8);
        pp += __shfl_xor_sync(0xffffffffu, pp, 2, 8);
        pp += __shfl_xor_sync(0xffffffffu, pp, 4, 8);
        float p = v ? __expf(beta * pp) : 0.f;
        s += p;
        a.x += p * sv.x; a.y += p * sv.y; a.z += p * sv.z; a.w += p * sv.w;

        v = nv; sv = nsv;
    }

#pragma unroll
    for (int off = 8; off <= 16; off <<= 1) {
        s += __shfl_xor_sync(0xffffffffu, s, off);
        a.x += __shfl_xor_sync(0xffffffffu, a.x, off);
        a.y += __shfl_xor_sync(0xffffffffu, a.y, off);
        a.z += __shfl_xor_sync(0xffffffffu, a.z, off);
        a.w += __shfl_xor_sync(0xffffffffu, a.w, off);
    }

    float ps = __expf(beta * cs);
    s += ps;
    a.x += ps * dv.x; a.y += ps * dv.y; a.z += ps * dv.z; a.w += ps * dv.w;

    if (sub >= 4) {
        float4* out4 = (float4*)(outSel ? g_bufB : g_bufA);
        out4[(long)node * 4 + (sub - 4)] = scl4(a, 1.0f / s);
    }
}

// ---------------- out = log_softmax(h @ W2 + b2), warp-per-row ----------------
__global__ void k_gemm2(float* __restrict__ out, int n) {
    __shared__ float sW[HID * NC];
    __shared__ float sB[NC];
    for (int i = threadIdx.x; i < HID * NC; i += blockDim.x) sW[i] = cW2[i];
    if (threadIdx.x < NC) sB[threadIdx.x] = cB2[threadIdx.x];
    __syncthreads();

    int warp = threadIdx.x >> 5, lane = threadIdx.x & 31;
    int row = blockIdx.x * (blockDim.x >> 5) + warp;
    if (row >= n) return;

    const float* h = g_bufA;
    float hv = (lane < HID) ? h[(long)row * HID + lane] : 0.f;
    float z0 = sB[lane], z1 = sB[lane + 32];
#pragma unroll
    for (int k = 0; k < HID; k++) {
        float hk = __shfl_sync(0xffffffffu, hv, k);
        z0 += hk * sW[k * NC + lane];
        z1 += hk * sW[k * NC + 32 + lane];
    }
    float mx = fmaxf(z0, z1);
#pragma unroll
    for (int off = 16; off > 0; off >>= 1) mx = fmaxf(mx, __shfl_xor_sync(0xffffffffu, mx, off));
    float p = __expf(z0 - mx) + __expf(z1 - mx);
#pragma unroll
    for (int off = 16; off > 0; off >>= 1) p += __shfl_xor_sync(0xffffffffu, p, off);
    float lse = mx + __logf(p);
    out[(long)row * NC + lane] = z0 - lse;
    out[(long)row * NC + 32 + lane] = z1 - lse;
}

// ---------------- launch ----------------
extern "C" void kernel_launch(void* const* d_in, const int* in_sizes, int n_in,
                              void* d_out, int out_size) {
    const float* x = (const float*)d_in[0];
    const int* ei = (const int*)d_in[1];
    const float* W1 = (const float*)d_in[2];
    const float* b1 = (const float*)d_in[3];
    const float* W2 = (const float*)d_in[4];
    const float* b2 = (const float*)d_in[5];
    const float* beta1 = (const float*)d_in[6];
    const float* beta2 = (const float*)d_in[7];
    float* out = (float*)d_out;

    int N = in_sizes[0] / FIN;
    int E = in_sizes[1] / 2;

    cudaMemcpyToSymbolAsync(cW2, W2, HID * NC * sizeof(float), 0, cudaMemcpyDeviceToDevice, 0);
    cudaMemcpyToSymbolAsync(cB2, b2, NC * sizeof(float), 0, cudaMemcpyDeviceToDevice, 0);

    static int smemSet = 0;
    if (!smemSet) {
        cudaFuncSetAttribute(k_gemm1, cudaFuncAttributeMaxDynamicSharedMemorySize, G1_SMEM_BYTES);
        smemSet = 1;
    }

    int NB = (N + 1023) / 1024;

    // kernels: zero(1) hist(2) presum(3) gemm1(4=profiled) scanout(5) scatter(6) ...
    k_zero<<<(N + 255) / 256, 256>>>(N);
    k_hist<<<(E / 4 + 255) / 256, 256>>>(ei, E);
    k_presum<<<NB, 1024>>>(N);
    k_gemm1<<<(N + 255) / 256, 128, G1_SMEM_BYTES>>>((const float4*)x, W1, b1, N);
    k_scanout<<<NB, 1024>>>(N);
    k_scatter<<<(E / 4 + 255) / 256, 256>>>(ei, E);

    // layer 1: g_row -> bufB
    k_agnn<<<(N + 7) / 8, 256>>>(beta1, 1, N);

    // layer 2: bufB -> g_row -> bufA
    k_norm<<<(N + 255) / 256, 256>>>(N);
    k_agnn<<<(N + 7) / 8, 256>>>(beta2, 0, N);

    // MLP out + log_softmax
    k_gemm2<<<(N + 7) / 8, 256>>>(out, N);
}

// round 7
// speedup vs baseline: 1.8428x; 1.0140x over previous
#include <cuda_runtime.h>

#define NN 100000
#define NE 3200000
#define FIN 512
#define HID 16
#define NC 64

// ---------------- scratch ----------------
__device__ __align__(16) float g_bufA[NN * HID];
__device__ __align__(128) float g_rowA[NN * 32];   // per node: [hn[16] | h_raw[16]]
__device__ __align__(128) float g_rowB[NN * 32];
__device__ int g_counts[NN + 1];
__device__ int g_rowptr[NN + 1];
__device__ int g_cursor[NN];
__device__ int g_colsrc[NE];
__device__ int g_bsum[128];

__constant__ __align__(16) float cW2[HID * NC];
__constant__ __align__(16) float cB2[NC];

// ---------------- helpers ----------------
__device__ __forceinline__ float d4(float4 a, float4 b) {
    return a.x * b.x + a.y * b.y + a.z * b.z + a.w * b.w;
}
__device__ __forceinline__ float4 scl4(float4 a, float c) {
    return make_float4(a.x * c, a.y * c, a.z * c, a.w * c);
}
__device__ __forceinline__ unsigned long long pk2(float a, float b) {
    unsigned long long r;
    asm("mov.b64 %0, {%1, %2};" : "=l"(r) : "f"(a), "f"(b));
    return r;
}
__device__ __forceinline__ void upk2(unsigned long long v, float& a, float& b) {
    asm("mov.b64 {%0, %1}, %2;" : "=f"(a), "=f"(b) : "l"(v));
}
__device__ __forceinline__ void ffma2(unsigned long long& d, unsigned long long a, unsigned long long b) {
    asm("fma.rn.f32x2 %0, %1, %2, %0;" : "+l"(d) : "l"(a), "l"(b));
}

// ---------------- CSR build ----------------
__global__ void k_zero(int n) {
    int i = blockIdx.x * blockDim.x + threadIdx.x;
    if (i < n) g_counts[i] = 0;
}

__global__ void k_hist(const int* __restrict__ ei, int E) {
    int t = blockIdx.x * blockDim.x + threadIdx.x;
    int E4 = E >> 2;
    const int4* d4p = (const int4*)(ei + E);
    if (t < E4) {
        int4 d = __ldg(d4p + t);
        atomicAdd(&g_counts[d.x], 1);
        atomicAdd(&g_counts[d.y], 1);
        atomicAdd(&g_counts[d.z], 1);
        atomicAdd(&g_counts[d.w], 1);
    }
    if (t == 0) {
        for (int e = E4 * 4; e < E; e++) atomicAdd(&g_counts[ei[E + e]], 1);
    }
}

__global__ void __launch_bounds__(1024) k_presum(int n) {
    int t = threadIdx.x, lane = t & 31, w = t >> 5;
    int i = blockIdx.x * 1024 + t;
    int v = (i < n) ? g_counts[i] : 0;
#pragma unroll
    for (int off = 16; off > 0; off >>= 1) v += __shfl_xor_sync(0xffffffffu, v, off);
    __shared__ int ws[32];
    if (lane == 0) ws[w] = v;
    __syncthreads();
    if (t < 32) {
        int s = ws[t];
#pragma unroll
        for (int off = 16; off > 0; off >>= 1) s += __shfl_xor_sync(0xffffffffu, s, off);
        if (t == 0) g_bsum[blockIdx.x] = s;
    }
}

__global__ void __launch_bounds__(1024) k_scanout(int n) {
    int t = threadIdx.x, lane = t & 31, w = t >> 5;
    __shared__ int wsum[32];
    __shared__ int s_boff;

    if (w == 0) {
        int s = 0;
#pragma unroll
        for (int k2 = 0; k2 < 4; k2++) {
            int j = lane + 32 * k2;
            if (j < blockIdx.x) s += g_bsum[j];
        }
#pragma unroll
        for (int off = 16; off > 0; off >>= 1) s += __shfl_xor_sync(0xffffffffu, s, off);
        if (lane == 0) s_boff = s;
    }

    int i = blockIdx.x * 1024 + t;
    int v = (i < n) ? g_counts[i] : 0;
    int x = v;
#pragma unroll
    for (int off = 1; off < 32; off <<= 1) {
        int y = __shfl_up_sync(0xffffffffu, x, off);
        if (lane >= off) x += y;
    }
    if (lane == 31) wsum[w] = x;
    __syncthreads();
    if (w == 0) {
        int y = wsum[lane];
        int inc = y;
#pragma unroll
        for (int off = 1; off < 32; off <<= 1) {
            int z = __shfl_up_sync(0xffffffffu, inc, off);
            if (lane >= off) inc += z;
        }
        wsum[lane] = inc - y;
    }
    __syncthreads();
    int excl = s_boff + wsum[w] + (x - v);
    if (i <= n) {
        g_rowptr[i] = excl;
        if (i < n) g_cursor[i] = excl;
    }
}

__global__ void k_scatter(const int* __restrict__ ei, int E) {
    int t = blockIdx.x * blockDim.x + threadIdx.x;
    int E4 = E >> 2;
    const int4* s4p = (const int4*)ei;
    const int4* d4p = (const int4*)(ei + E);
    if (t < E4) {
        int4 s = __ldg(s4p + t);
        int4 d = __ldg(d4p + t);
        int p;
        p = atomicAdd(&g_cursor[d.x], 1); g_colsrc[p] = s.x;
        p = atomicAdd(&g_cursor[d.y], 1); g_colsrc[p] = s.y;
        p = atomicAdd(&g_cursor[d.z], 1); g_colsrc[p] = s.z;
        p = atomicAdd(&g_cursor[d.w], 1); g_colsrc[p] = s.w;
    }
    if (t == 0) {
        for (int e = E4 * 4; e < E; e++) {
            int p = atomicAdd(&g_cursor[ei[E + e]], 1);
            g_colsrc[p] = ei[e];
        }
    }
}

// ---------------- fused gemm1 + normalize + g_rowA build, double-buffered ----------------
#define TILE_STRIDE 20
#define TILE_FLOATS (256 * TILE_STRIDE)
#define G1_SMEM_BYTES ((FIN * HID + 2 * TILE_FLOATS) * 4)
__global__ void __launch_bounds__(128) k_gemm1(const float4* __restrict__ x4,
                                               const float* __restrict__ W1,
                                               const float* __restrict__ b1, int n) {
    extern __shared__ float dsm[];
    float* sW = dsm;                         // 8192 floats
    float* tiles = dsm + FIN * HID;          // 2 x [256][20]
    int t = threadIdx.x;
    int row0 = blockIdx.x * 256;

    const float4* w4g = (const float4*)W1;
    float4* w4s = (float4*)sW;
#pragma unroll
    for (int i = 0; i < 16; i++) w4s[i * 128 + t] = __ldg(&w4g[i * 128 + t]);

    unsigned long long accA[8], accB[8];
#pragma unroll
    for (int j = 0; j < 8; j++) {
        unsigned long long b = pk2(__ldg(&b1[2 * j]), __ldg(&b1[2 * j + 1]));
        accA[j] = b; accB[j] = b;
    }

    float4 pf[8];
#pragma unroll
    for (int i = 0; i < 8; i++) {
        int fi = i * 128 + t, r = fi >> 2, c4 = fi & 3;
        int gr = row0 + r;
        pf[i] = make_float4(0.f, 0.f, 0.f, 0.f);
        if (gr < n) pf[i] = __ldg(&x4[(long)gr * (FIN / 4) + c4]);
    }

#pragma unroll 1
    for (int kt = 0; kt < 32; kt++) {
        float* tile = tiles + (kt & 1) * TILE_FLOATS;
#pragma unroll
        for (int i = 0; i < 8; i++) {
            int fi = i * 128 + t, r = fi >> 2, c4 = fi & 3;
            *(float4*)&tile[r * TILE_STRIDE + c4 * 4] = pf[i];
        }
        __syncthreads();
        if (kt < 31) {
#pragma unroll
            for (int i = 0; i < 8; i++) {
                int fi = i * 128 + t, r = fi >> 2, c4 = fi & 3;
                int gr = row0 + r;
                pf[i] = make_float4(0.f, 0.f, 0.f, 0.f);
                if (gr < n) pf[i] = __ldg(&x4[(long)gr * (FIN / 4) + (kt + 1) * 4 + c4]);
            }
        }
#pragma unroll
        for (int c4 = 0; c4 < 4; c4++) {
            float4 xa = *(const float4*)&tile[t * TILE_STRIDE + c4 * 4];
            float4 xb = *(const float4*)&tile[(t + 128) * TILE_STRIDE + c4 * 4];
#pragma unroll
            for (int c = 0; c < 4; c++) {
                float xsa = (c == 0) ? xa.x : (c == 1) ? xa.y : (c == 2) ? xa.z : xa.w;
                float xsb = (c == 0) ? xb.x : (c == 1) ? xb.y : (c == 2) ? xb.z : xb.w;
                unsigned long long xxa = pk2(xsa, xsa);
                unsigned long long xxb = pk2(xsb, xsb);
                const ulonglong2* w = (const ulonglong2*)&sW[(kt * 16 + c4 * 4 + c) * HID];
                ulonglong2 wa = w[0], wb = w[1], wc = w[2], wd = w[3];
                ffma2(accA[0], xxa, wa.x); ffma2(accA[1], xxa, wa.y);
                ffma2(accA[2], xxa, wb.x); ffma2(accA[3], xxa, wb.y);
                ffma2(accA[4], xxa, wc.x); ffma2(accA[5], xxa, wc.y);
                ffma2(accA[6], xxa, wd.x); ffma2(accA[7], xxa, wd.y);
                ffma2(accB[0], xxb, wa.x); ffma2(accB[1], xxb, wa.y);
                ffma2(accB[2], xxb, wb.x); ffma2(accB[3], xxb, wb.y);
                ffma2(accB[4], xxb, wc.x); ffma2(accB[5], xxb, wc.y);
                ffma2(accB[6], xxb, wd.x); ffma2(accB[7], xxb, wd.y);
            }
        }
    }

#pragma unroll
    for (int half = 0; half < 2; half++) {
        int row = row0 + t + half * 128;
        if (row >= n) continue;
        unsigned long long* acc = half ? accB : accA;
        float o[16];
        float ss = 0.f;
#pragma unroll
        for (int j = 0; j < 8; j++) {
            float a, b;
            upk2(acc[j], a, b);
            a = fmaxf(a, 0.f);
            b = fmaxf(b, 0.f);
            o[2 * j] = a; o[2 * j + 1] = b;
            ss += a * a + b * b;
        }
        float inv = 1.0f / fmaxf(sqrtf(ss), 1e-12f);
        float4* r4 = (float4*)&g_rowA[(long)row * 32];
#pragma unroll
        for (int j = 0; j < 4; j++) {
            float4 raw = make_float4(o[4 * j], o[4 * j + 1], o[4 * j + 2], o[4 * j + 3]);
            r4[j] = scl4(raw, inv);
            r4[4 + j] = raw;
        }
    }
}

// ---------------- AGNN layer: warp/node, 8 edges/iter (2 groups), prefetched ----------------
// logits bounded by |beta| -> direct softmax (no max subtraction).
// Reads rowIn; outMode 0: write rowOut (normalized + raw). 1: write g_bufA.
__global__ void k_agnn(const float* __restrict__ beta_p,
                       const float4* __restrict__ rowIn,
                       float4* __restrict__ rowOut,
                       int outMode, int n) {
    int lane = threadIdx.x & 31;
    int warp = threadIdx.x >> 5;
    int node = blockIdx.x * 8 + warp;
    if (node >= n) return;
    int sub = lane & 7;
    int slot = lane >> 3;
    float beta = __ldg(beta_p);

    float4 dv = rowIn[(long)node * 8 + sub];

    float cs = (sub < 4) ? d4(dv, dv) : 0.f;
    cs += __shfl_xor_sync(0xffffffffu, cs, 1, 8);
    cs += __shfl_xor_sync(0xffffffffu, cs, 2, 8);
    cs += __shfl_xor_sync(0xffffffffu, cs, 4, 8);

    int e0 = g_rowptr[node];
    int cnt = g_rowptr[node + 1] - e0;

    float s = 0.f;
    float4 a = make_float4(0.f, 0.f, 0.f, 0.f);

    int iA = slot, iB = 4 + slot;
    bool vA = iA < cnt, vB = iB < cnt;
    int snA = vA ? __ldg(&g_colsrc[e0 + iA]) : node;
    int snB = vB ? __ldg(&g_colsrc[e0 + iB]) : node;
    float4 svA = __ldg(&rowIn[(long)snA * 8 + sub]);
    float4 svB = __ldg(&rowIn[(long)snB * 8 + sub]);

    for (int base = 0; base < cnt; base += 8) {
        int jA = base + 8 + slot, jB = base + 12 + slot;
        bool wA = jA < cnt, wB = jB < cnt;
        int tnA = wA ? __ldg(&g_colsrc[e0 + jA]) : node;
        int tnB = wB ? __ldg(&g_colsrc[e0 + jB]) : node;
        float4 nvA = __ldg(&rowIn[(long)tnA * 8 + sub]);
        float4 nvB = __ldg(&rowIn[(long)tnB * 8 + sub]);

        float pA = (sub < 4) ? d4(dv, svA) : 0.f;
        float pB = (sub < 4) ? d4(dv, svB) : 0.f;
        pA += __shfl_xor_sync(0xffffffffu, pA, 1, 8);
        pB += __shfl_xor_sync(0xffffffffu, pB, 1, 8);
        pA += __shfl_xor_sync(0xffffffffu, pA, 2, 8);
        pB += __shfl_xor_sync(0xffffffffu, pB, 2, 8);
        pA += __shfl_xor_sync(0xffffffffu, pA, 4, 8);
        pB += __shfl_xor_sync(0xffffffffu, pB, 4, 8);
        float eA = vA ? __expf(beta * pA) : 0.f;
        float eB = vB ? __expf(beta * pB) : 0.f;
        s += eA + eB;
        a.x += eA * svA.x + eB * svB.x;
        a.y += eA * svA.y + eB * svB.y;
        a.z += eA * svA.z + eB * svB.z;
        a.w += eA * svA.w + eB * svB.w;

        vA = wA; vB = wB; svA = nvA; svB = nvB;
    }

#pragma unroll
    for (int off = 8; off <= 16; off <<= 1) {
        s += __shfl_xor_sync(0xffffffffu, s, off);
        a.x += __shfl_xor_sync(0xffffffffu, a.x, off);
        a.y += __shfl_xor_sync(0xffffffffu, a.y, off);
        a.z += __shfl_xor_sync(0xffffffffu, a.z, off);
        a.w += __shfl_xor_sync(0xffffffffu, a.w, off);
    }

    float ps = __expf(beta * cs);
    s += ps;
    a.x += ps * dv.x; a.y += ps * dv.y; a.z += ps * dv.z; a.w += ps * dv.w;

    if (sub >= 4) {
        float inv = 1.0f / s;
        float4 o = scl4(a, inv);
        if (outMode == 0) {
            // fused normalize: reduce ||o||^2 across lanes sub=4..7
            float ss = d4(o, o);
            ss += __shfl_xor_sync(0xffffffffu, ss, 1, 8);
            ss += __shfl_xor_sync(0xffffffffu, ss, 2, 8);
            float invn = 1.0f / fmaxf(sqrtf(ss), 1e-12f);
            rowOut[(long)node * 8 + (sub - 4)] = scl4(o, invn);
            rowOut[(long)node * 8 + sub] = o;
        } else {
            float4* out4 = (float4*)g_bufA;
            out4[(long)node * 4 + (sub - 4)] = o;
        }
    }
}

// ---------------- out = log_softmax(h @ W2 + b2), warp-per-row ----------------
__global__ void k_gemm2(float* __restrict__ out, int n) {
    __shared__ float sW[HID * NC];
    __shared__ float sB[NC];
    for (int i = threadIdx.x; i < HID * NC; i += blockDim.x) sW[i] = cW2[i];
    if (threadIdx.x < NC) sB[threadIdx.x] = cB2[threadIdx.x];
    __syncthreads();

    int warp = threadIdx.x >> 5, lane = threadIdx.x & 31;
    int row = blockIdx.x * (blockDim.x >> 5) + warp;
    if (row >= n) return;

    const float* h = g_bufA;
    float hv = (lane < HID) ? h[(long)row * HID + lane] : 0.f;
    float z0 = sB[lane], z1 = sB[lane + 32];
#pragma unroll
    for (int k = 0; k < HID; k++) {
        float hk = __shfl_sync(0xffffffffu, hv, k);
        z0 += hk * sW[k * NC + lane];
        z1 += hk * sW[k * NC + 32 + lane];
    }
    float mx = fmaxf(z0, z1);
#pragma unroll
    for (int off = 16; off > 0; off >>= 1) mx = fmaxf(mx, __shfl_xor_sync(0xffffffffu, mx, off));
    float p = __expf(z0 - mx) + __expf(z1 - mx);
#pragma unroll
    for (int off = 16; off > 0; off >>= 1) p += __shfl_xor_sync(0xffffffffu, p, off);
    float lse = mx + __logf(p);
    out[(long)row * NC + lane] = z0 - lse;
    out[(long)row * NC + 32 + lane] = z1 - lse;
}

// ---------------- launch ----------------
extern "C" void kernel_launch(void* const* d_in, const int* in_sizes, int n_in,
                              void* d_out, int out_size) {
    const float* x = (const float*)d_in[0];
    const int* ei = (const int*)d_in[1];
    const float* W1 = (const float*)d_in[2];
    const float* b1 = (const float*)d_in[3];
    const float* W2 = (const float*)d_in[4];
    const float* b2 = (const float*)d_in[5];
    const float* beta1 = (const float*)d_in[6];
    const float* beta2 = (const float*)d_in[7];
    float* out = (float*)d_out;

    int N = in_sizes[0] / FIN;
    int E = in_sizes[1] / 2;

    cudaMemcpyToSymbolAsync(cW2, W2, HID * NC * sizeof(float), 0, cudaMemcpyDeviceToDevice, 0);
    cudaMemcpyToSymbolAsync(cB2, b2, NC * sizeof(float), 0, cudaMemcpyDeviceToDevice, 0);

    static int smemSet = 0;
    if (!smemSet) {
        cudaFuncSetAttribute(k_gemm1, cudaFuncAttributeMaxDynamicSharedMemorySize, G1_SMEM_BYTES);
        smemSet = 1;
    }

    int NB = (N + 1023) / 1024;

    float4* rowA4 = nullptr;
    float4* rowB4 = nullptr;
    cudaGetSymbolAddress((void**)&rowA4, g_rowA);
    cudaGetSymbolAddress((void**)&rowB4, g_rowB);

    // zero(1) hist(2) presum(3) gemm1(4=profiled) scanout(5) scatter(6) ...
    k_zero<<<(N + 255) / 256, 256>>>(N);
    k_hist<<<(E / 4 + 255) / 256, 256>>>(ei, E);
    k_presum<<<NB, 1024>>>(N);
    k_gemm1<<<(N + 255) / 256, 128, G1_SMEM_BYTES>>>((const float4*)x, W1, b1, N);
    k_scanout<<<NB, 1024>>>(N);
    k_scatter<<<(E / 4 + 255) / 256, 256>>>(ei, E);

    // layer 1: rowA -> rowB (fused normalize; separate buffers, no race)
    k_agnn<<<(N + 7) / 8, 256>>>(beta1, rowA4, rowB4, 0, N);
    // layer 2: rowB -> bufA
    k_agnn<<<(N + 7) / 8, 256>>>(beta2, rowB4, nullptr, 1, N);

    // MLP out + log_softmax
    k_gemm2<<<(N + 7) / 8, 256>>>(out, N);
}

// round 8
// speedup vs baseline: 2.4967x; 1.3548x over previous
#include <cuda_runtime.h>

#define NN 100000
#define NE 3200000
#define FIN 512
#define HID 16
#define NC 64

// ---------------- scratch ----------------
__device__ __align__(16) float g_bufA[NN * HID];
__device__ __align__(128) float g_rowA[NN * 32];   // per node: [hn[16] | h_raw[16]]
__device__ __align__(128) float g_rowB[NN * 32];
__device__ int g_counts[NN + 1];
__device__ int g_rowptr[NN + 1];
__device__ int g_cursor[NN];
__device__ int g_colsrc[NE];
__device__ unsigned long long g_pub[128];          // decoupled-lookback: status<<32 | value

// ---------------- helpers ----------------
__device__ __forceinline__ float d4(float4 a, float4 b) {
    return a.x * b.x + a.y * b.y + a.z * b.z + a.w * b.w;
}
__device__ __forceinline__ float4 scl4(float4 a, float c) {
    return make_float4(a.x * c, a.y * c, a.z * c, a.w * c);
}
__device__ __forceinline__ unsigned long long pk2(float a, float b) {
    unsigned long long r;
    asm("mov.b64 %0, {%1, %2};" : "=l"(r) : "f"(a), "f"(b));
    return r;
}
__device__ __forceinline__ void upk2(unsigned long long v, float& a, float& b) {
    asm("mov.b64 {%0, %1}, %2;" : "=f"(a), "=f"(b) : "l"(v));
}
__device__ __forceinline__ void ffma2(unsigned long long& d, unsigned long long a, unsigned long long b) {
    asm("fma.rn.f32x2 %0, %1, %2, %0;" : "+l"(d) : "l"(a), "l"(b));
}
__device__ __forceinline__ void cp16(unsigned int s, const void* g) {
    asm volatile("cp.async.cg.shared.global [%0], [%1], 16;" :: "r"(s), "l"(g));
}
#define CP_COMMIT() asm volatile("cp.async.commit_group;")
#define CP_WAIT1()  asm volatile("cp.async.wait_group 1;" ::: "memory")
#define CP_WAIT0()  asm volatile("cp.async.wait_group 0;" ::: "memory")

// ---------------- launch 1: hist (+ zero lookback flags) ----------------
__global__ void k_hist(const int* __restrict__ ei, int E) {
    int t = blockIdx.x * blockDim.x + threadIdx.x;
    if (blockIdx.x == 0 && threadIdx.x < 128) g_pub[threadIdx.x] = 0ull;
    int E4 = E >> 2;
    const int4* d4p = (const int4*)(ei + E);
    if (t < E4) {
        int4 d = __ldg(d4p + t);
        atomicAdd(&g_counts[d.x], 1);
        atomicAdd(&g_counts[d.y], 1);
        atomicAdd(&g_counts[d.z], 1);
        atomicAdd(&g_counts[d.w], 1);
    }
    if (t == 0) {
        for (int e = E4 * 4; e < E; e++) atomicAdd(&g_counts[ei[E + e]], 1);
    }
}

// ---------------- launch 2: single-pass scan (decoupled lookback) ----------------
// Reads counts -> rowptr/cursor; zeroes counts for the next run.
__global__ void __launch_bounds__(1024) k_scan(int n) {
    int b = blockIdx.x, t = threadIdx.x, lane = t & 31, w = t >> 5;
    __shared__ int wsum[32];
    __shared__ int s_boff;

    int i = b * 1024 + t;
    int v = (i < n) ? g_counts[i] : 0;
    if (i < n) g_counts[i] = 0;          // re-zero for next run

    int x = v;
#pragma unroll
    for (int off = 1; off < 32; off <<= 1) {
        int y = __shfl_up_sync(0xffffffffu, x, off);
        if (lane >= off) x += y;
    }
    if (lane == 31) wsum[w] = x;
    __syncthreads();

    if (w == 0) {
        int y = wsum[lane];
        int inc = y;
#pragma unroll
        for (int off = 1; off < 32; off <<= 1) {
            int z = __shfl_up_sync(0xffffffffu, inc, off);
            if (lane >= off) inc += z;
        }
        int agg = __shfl_sync(0xffffffffu, inc, 31);
        wsum[lane] = inc - y;            // exclusive warp offsets
        // publish aggregate ASAP
        if (lane == 0) {
            if (b == 0) atomicExch(&g_pub[0], (2ull << 32) | (unsigned)agg);
            else        atomicExch(&g_pub[b], (1ull << 32) | (unsigned)agg);
        }
        if (b > 0) {
            long long run = 0;
            int base_j = b - 1;
            while (true) {
                int j = base_j - lane;
                unsigned long long p = 0ull;
                if (j >= 0) {
                    do { p = atomicAdd(&g_pub[j], 0ull); } while ((unsigned)(p >> 32) == 0u);
                }
                unsigned st = (j >= 0) ? (unsigned)(p >> 32) : 1u;
                unsigned val = (j >= 0) ? (unsigned)p : 0u;
                unsigned pmask = __ballot_sync(0xffffffffu, st == 2u);
                unsigned contrib;
                bool done;
                if (pmask) {
                    int firstP = __ffs(pmask) - 1;   // lowest lane with P = largest j
                    contrib = (lane <= firstP) ? val : 0u;
                    done = true;
                } else {
                    contrib = val;
                    done = false;
                }
#pragma unroll
                for (int off = 16; off > 0; off >>= 1)
                    contrib += __shfl_xor_sync(0xffffffffu, contrib, off);
                run += contrib;
                if (done) break;
                base_j -= 32;
            }
            if (lane == 0) {
                atomicExch(&g_pub[b], (2ull << 32) | (unsigned)(run + agg));
                s_boff = (int)run;
            }
        } else if (lane == 0) {
            s_boff = 0;
        }
    }
    __syncthreads();

    int excl = s_boff + wsum[w] + (x - v);
    if (i <= n) {
        g_rowptr[i] = excl;
        if (i < n) g_cursor[i] = excl;
    }
}

// ---------------- launch 3: fused gemm1 (cp.async) + scatter ----------------
#define TILE_STRIDE 20
#define TILE_FLOATS (256 * TILE_STRIDE)
#define G1_SMEM_BYTES ((FIN * HID + 2 * TILE_FLOATS) * 4)

__global__ void __launch_bounds__(256) k_fused(const float4* __restrict__ x4,
                                               const float* __restrict__ W1,
                                               const float* __restrict__ b1,
                                               const int* __restrict__ ei,
                                               int E, int n, int GB) {
    int t = threadIdx.x;
    if ((int)blockIdx.x >= GB) {
        // ---- scatter part ----
        int tt = (blockIdx.x - GB) * 256 + t;
        int E4 = E >> 2;
        const int4* s4p = (const int4*)ei;
        const int4* d4p = (const int4*)(ei + E);
        if (tt < E4) {
            int4 s = __ldg(s4p + tt);
            int4 d = __ldg(d4p + tt);
            int p;
            p = atomicAdd(&g_cursor[d.x], 1); g_colsrc[p] = s.x;
            p = atomicAdd(&g_cursor[d.y], 1); g_colsrc[p] = s.y;
            p = atomicAdd(&g_cursor[d.z], 1); g_colsrc[p] = s.z;
            p = atomicAdd(&g_cursor[d.w], 1); g_colsrc[p] = s.w;
        }
        if ((int)blockIdx.x == GB && t == 0) {
            for (int e = E4 * 4; e < E; e++) {
                int p = atomicAdd(&g_cursor[ei[E + e]], 1);
                g_colsrc[p] = ei[e];
            }
        }
        return;
    }

    // ---- gemm1 part: 256 threads, 1 row/thread, cp.async double-buffer ----
    extern __shared__ float dsm[];
    float* sW = dsm;                      // 8192 floats
    float* tiles = dsm + FIN * HID;       // 2 x [256][20]
    unsigned int sW_u = (unsigned int)__cvta_generic_to_shared(sW);
    unsigned int tiles_u = (unsigned int)__cvta_generic_to_shared(tiles);
    int row0 = blockIdx.x * 256;

    // stage W1 (2048 float4, 8 per thread) + chunk0 in group 0
    const float4* w4g = (const float4*)W1;
#pragma unroll
    for (int i = 0; i < 8; i++)
        cp16(sW_u + (i * 256 + t) * 16, &w4g[i * 256 + t]);
#pragma unroll
    for (int q = 0; q < 4; q++) {
        int id = q * 256 + t, r = id >> 2, c4 = id & 3;
        int gr = min(row0 + r, n - 1);
        cp16(tiles_u + (r * TILE_STRIDE + c4 * 4) * 4, &x4[(long)gr * (FIN / 4) + c4]);
    }
    CP_COMMIT();
    // chunk1 -> group 1
#pragma unroll
    for (int q = 0; q < 4; q++) {
        int id = q * 256 + t, r = id >> 2, c4 = id & 3;
        int gr = min(row0 + r, n - 1);
        cp16(tiles_u + (TILE_FLOATS + r * TILE_STRIDE + c4 * 4) * 4, &x4[(long)gr * (FIN / 4) + 4 + c4]);
    }
    CP_COMMIT();

    unsigned long long acc[8];
#pragma unroll
    for (int j = 0; j < 8; j++) acc[j] = pk2(__ldg(&b1[2 * j]), __ldg(&b1[2 * j + 1]));

#pragma unroll 1
    for (int kt = 0; kt < 32; kt++) {
        if (kt == 31) { CP_WAIT0(); } else { CP_WAIT1(); }
        __syncthreads();
        float* tile = tiles + (kt & 1) * TILE_FLOATS;
#pragma unroll
        for (int c4 = 0; c4 < 4; c4++) {
            float4 xv = *(const float4*)&tile[t * TILE_STRIDE + c4 * 4];
#pragma unroll
            for (int c = 0; c < 4; c++) {
                float xs = (c == 0) ? xv.x : (c == 1) ? xv.y : (c == 2) ? xv.z : xv.w;
                unsigned long long xx = pk2(xs, xs);
                const ulonglong2* w = (const ulonglong2*)&sW[(kt * 16 + c4 * 4 + c) * HID];
                ulonglong2 wa = w[0], wb = w[1], wc = w[2], wd = w[3];
                ffma2(acc[0], xx, wa.x); ffma2(acc[1], xx, wa.y);
                ffma2(acc[2], xx, wb.x); ffma2(acc[3], xx, wb.y);
                ffma2(acc[4], xx, wc.x); ffma2(acc[5], xx, wc.y);
                ffma2(acc[6], xx, wd.x); ffma2(acc[7], xx, wd.y);
            }
        }
        __syncthreads();
        if (kt + 2 < 32) {
#pragma unroll
            for (int q = 0; q < 4; q++) {
                int id = q * 256 + t, r = id >> 2, c4 = id & 3;
                int gr = min(row0 + r, n - 1);
                cp16(tiles_u + ((kt & 1) * TILE_FLOATS + r * TILE_STRIDE + c4 * 4) * 4,
                     &x4[(long)gr * (FIN / 4) + (kt + 2) * 4 + c4]);
            }
            CP_COMMIT();
        }
    }

    int row = row0 + t;
    if (row >= n) return;
    float o[16];
    float ss = 0.f;
#pragma unroll
    for (int j = 0; j < 8; j++) {
        float a, b;
        upk2(acc[j], a, b);
        a = fmaxf(a, 0.f);
        b = fmaxf(b, 0.f);
        o[2 * j] = a; o[2 * j + 1] = b;
        ss += a * a + b * b;
    }
    float inv = 1.0f / fmaxf(sqrtf(ss), 1e-12f);
    float4* r4 = (float4*)&g_rowA[(long)row * 32];
#pragma unroll
    for (int j = 0; j < 4; j++) {
        float4 raw = make_float4(o[4 * j], o[4 * j + 1], o[4 * j + 2], o[4 * j + 3]);
        r4[j] = scl4(raw, inv);
        r4[4 + j] = raw;
    }
}

// ---------------- launches 4,5: AGNN layer (2-stage col pipeline) ----------------
// logits bounded by |beta| -> direct softmax (no max subtraction).
__global__ void k_agnn(const float* __restrict__ beta_p,
                       const float4* __restrict__ rowIn,
                       float4* __restrict__ rowOut,
                       int outMode, int n) {
    int lane = threadIdx.x & 31;
    int warp = threadIdx.x >> 5;
    int node = blockIdx.x * 8 + warp;
    if (node >= n) return;
    int sub = lane & 7;
    int slot = lane >> 3;
    float beta = __ldg(beta_p);

    float4 dv = rowIn[(long)node * 8 + sub];

    float cs = (sub < 4) ? d4(dv, dv) : 0.f;
    cs += __shfl_xor_sync(0xffffffffu, cs, 1, 8);
    cs += __shfl_xor_sync(0xffffffffu, cs, 2, 8);
    cs += __shfl_xor_sync(0xffffffffu, cs, 4, 8);

    int e0 = g_rowptr[node];
    int cnt = g_rowptr[node + 1] - e0;

    float s = 0.f;
    float4 a = make_float4(0.f, 0.f, 0.f, 0.f);

    // pipeline prologue: cols for iter 0 and 1; rows for iter 0
    bool vA0 = slot < cnt,      vB0 = slot + 4 < cnt;
    int cA0 = __ldg(&g_colsrc[vA0 ? e0 + slot : 0]);
    int cB0 = __ldg(&g_colsrc[vB0 ? e0 + slot + 4 : 0]);
    float4 rA0 = __ldg(&rowIn[(long)(vA0 ? cA0 : node) * 8 + sub]);
    float4 rB0 = __ldg(&rowIn[(long)(vB0 ? cB0 : node) * 8 + sub]);
    bool vA1 = slot + 8 < cnt,  vB1 = slot + 12 < cnt;
    int cA1 = __ldg(&g_colsrc[vA1 ? e0 + slot + 8 : 0]);
    int cB1 = __ldg(&g_colsrc[vB1 ? e0 + slot + 12 : 0]);

    for (int base = 0; base < cnt; base += 8) {
        // issue cols for iter+2
        bool vA2 = base + 16 + slot < cnt, vB2 = base + 20 + slot < cnt;
        int cA2 = __ldg(&g_colsrc[vA2 ? e0 + base + 16 + slot : 0]);
        int cB2 = __ldg(&g_colsrc[vB2 ? e0 + base + 20 + slot : 0]);
        // issue rows for iter+1 (col loaded a full iteration ago -> no stall)
        float4 rA1 = __ldg(&rowIn[(long)(vA1 ? cA1 : node) * 8 + sub]);
        float4 rB1 = __ldg(&rowIn[(long)(vB1 ? cB1 : node) * 8 + sub]);

        // math on iter's rows (two independent chains interleaved)
        float pA = (sub < 4) ? d4(dv, rA0) : 0.f;
        float pB = (sub < 4) ? d4(dv, rB0) : 0.f;
        pA += __shfl_xor_sync(0xffffffffu, pA, 1, 8);
        pB += __shfl_xor_sync(0xffffffffu, pB, 1, 8);
        pA += __shfl_xor_sync(0xffffffffu, pA, 2, 8);
        pB += __shfl_xor_sync(0xffffffffu, pB, 2, 8);
        pA += __shfl_xor_sync(0xffffffffu, pA, 4, 8);
        pB += __shfl_xor_sync(0xffffffffu, pB, 4, 8);
        float eA = vA0 ? __expf(beta * pA) : 0.f;
        float eB = vB0 ? __expf(beta * pB) : 0.f;
        s += eA + eB;
        a.x += eA * rA0.x + eB * rB0.x;
        a.y += eA * rA0.y + eB * rB0.y;
        a.z += eA * rA0.z + eB * rB0.z;
        a.w += eA * rA0.w + eB * rB0.w;

        // shift pipeline
        vA0 = vA1; vB0 = vB1; rA0 = rA1; rB0 = rB1;
        vA1 = vA2; vB1 = vB2; cA1 = cA2; cB1 = cB2;
    }

    // combine the 4 slot partials
#pragma unroll
    for (int off = 8; off <= 16; off <<= 1) {
        s += __shfl_xor_sync(0xffffffffu, s, off);
        a.x += __shfl_xor_sync(0xffffffffu, a.x, off);
        a.y += __shfl_xor_sync(0xffffffffu, a.y, off);
        a.z += __shfl_xor_sync(0xffffffffu, a.z, off);
        a.w += __shfl_xor_sync(0xffffffffu, a.w, off);
    }

    // implicit self-loop
    float ps = __expf(beta * cs);
    s += ps;
    a.x += ps * dv.x; a.y += ps * dv.y; a.z += ps * dv.z; a.w += ps * dv.w;

    if (sub >= 4) {
        float inv = 1.0f / s;
        float4 o = scl4(a, inv);
        if (outMode == 0) {
            float ss2 = d4(o, o);
            ss2 += __shfl_xor_sync(0xffffffffu, ss2, 1, 8);
            ss2 += __shfl_xor_sync(0xffffffffu, ss2, 2, 8);
            float invn = 1.0f / fmaxf(sqrtf(ss2), 1e-12f);
            rowOut[(long)node * 8 + (sub - 4)] = scl4(o, invn);
            rowOut[(long)node * 8 + sub] = o;
        } else {
            float4* out4 = (float4*)g_bufA;
            out4[(long)node * 4 + (sub - 4)] = o;
        }
    }
}

// ---------------- launch 6: out = log_softmax(h @ W2 + b2) ----------------
__global__ void k_gemm2(const float* __restrict__ W2, const float* __restrict__ b2,
                        float* __restrict__ out, int n) {
    __shared__ float sW[HID * NC];
    __shared__ float sB[NC];
    for (int i = threadIdx.x; i < HID * NC; i += blockDim.x) sW[i] = __ldg(&W2[i]);
    if (threadIdx.x < NC) sB[threadIdx.x] = __ldg(&b2[threadIdx.x]);
    __syncthreads();

    int warp = threadIdx.x >> 5, lane = threadIdx.x & 31;
    int row = blockIdx.x * (blockDim.x >> 5) + warp;
    if (row >= n) return;

    const float* h = g_bufA;
    float hv = (lane < HID) ? h[(long)row * HID + lane] : 0.f;
    float z0 = sB[lane], z1 = sB[lane + 32];
#pragma unroll
    for (int k = 0; k < HID; k++) {
        float hk = __shfl_sync(0xffffffffu, hv, k);
        z0 += hk * sW[k * NC + lane];
        z1 += hk * sW[k * NC + 32 + lane];
    }
    float mx = fmaxf(z0, z1);
#pragma unroll
    for (int off = 16; off > 0; off >>= 1) mx = fmaxf(mx, __shfl_xor_sync(0xffffffffu, mx, off));
    float p = __expf(z0 - mx) + __expf(z1 - mx);
#pragma unroll
    for (int off = 16; off > 0; off >>= 1) p += __shfl_xor_sync(0xffffffffu, p, off);
    float lse = mx + __logf(p);
    out[(long)row * NC + lane] = z0 - lse;
    out[(long)row * NC + 32 + lane] = z1 - lse;
}

// ---------------- launch ----------------
extern "C" void kernel_launch(void* const* d_in, const int* in_sizes, int n_in,
                              void* d_out, int out_size) {
    const float* x = (const float*)d_in[0];
    const int* ei = (const int*)d_in[1];
    const float* W1 = (const float*)d_in[2];
    const float* b1 = (const float*)d_in[3];
    const float* W2 = (const float*)d_in[4];
    const float* b2 = (const float*)d_in[5];
    const float* beta1 = (const float*)d_in[6];
    const float* beta2 = (const float*)d_in[7];
    float* out = (float*)d_out;

    int N = in_sizes[0] / FIN;
    int E = in_sizes[1] / 2;

    static int smemSet = 0;
    if (!smemSet) {
        cudaFuncSetAttribute(k_fused, cudaFuncAttributeMaxDynamicSharedMemorySize, G1_SMEM_BYTES);
        smemSet = 1;
    }

    float4* rowA4 = nullptr;
    float4* rowB4 = nullptr;
    cudaGetSymbolAddress((void**)&rowA4, g_rowA);
    cudaGetSymbolAddress((void**)&rowB4, g_rowB);

    int NBscan = (N + 1 + 1023) / 1024;     // cover rowptr[0..N]
    int GB = (N + 255) / 256;               // gemm1 blocks
    int SB = (E / 4 + 255) / 256;           // scatter blocks

    // 1: hist (+ zero lookback pub)
    k_hist<<<SB, 256>>>(ei, E);
    // 2: single-pass scan (also re-zeroes counts for next run)
    k_scan<<<NBscan, 1024>>>(N);
    // 3: fused gemm1 + scatter
    k_fused<<<GB + SB, 256, G1_SMEM_BYTES>>>((const float4*)x, W1, b1, ei, E, N, GB);
    // 4: agnn layer 1 (PROFILED SLOT)  rowA -> rowB
    k_agnn<<<(N + 7) / 8, 256>>>(beta1, rowA4, rowB4, 0, N);
    // 5: agnn layer 2  rowB -> bufA
    k_agnn<<<(N + 7) / 8, 256>>>(beta2, rowB4, nullptr, 1, N);
    // 6: MLP out + log_softmax
    k_gemm2<<<(N + 7) / 8, 256>>>(W2, b2, out, N);
}

// round 9
// speedup vs baseline: 2.6837x; 1.0749x over previous
#include <cuda_runtime.h>

#define NN 100000
#define NE 3200000
#define FIN 512
#define HID 16
#define NC 64
#define NCOL (NE + 8 * NN + 64)   // padded colsrc capacity (+slack for prefetch overrun)

// ---------------- scratch ----------------
__device__ __align__(16) float g_bufA[NN * HID];
__device__ __align__(128) float g_rowA[(NN + 1) * 32];   // +1: dummy zero row for pads
__device__ __align__(128) float g_rowB[(NN + 1) * 32];
__device__ int g_counts[NN + 1];
__device__ int g_cnt[NN];                                // real (unpadded) degree
__device__ int g_rowptr[NN + 1];
__device__ int g_cursor[NN];
__device__ int g_colsrc[NCOL];
__device__ unsigned long long g_pub[128];                // decoupled-lookback

// ---------------- helpers ----------------
__device__ __forceinline__ float d4(float4 a, float4 b) {
    return a.x * b.x + a.y * b.y + a.z * b.z + a.w * b.w;
}
__device__ __forceinline__ float4 scl4(float4 a, float c) {
    return make_float4(a.x * c, a.y * c, a.z * c, a.w * c);
}
__device__ __forceinline__ unsigned long long pk2(float a, float b) {
    unsigned long long r;
    asm("mov.b64 %0, {%1, %2};" : "=l"(r) : "f"(a), "f"(b));
    return r;
}
__device__ __forceinline__ void upk2(unsigned long long v, float& a, float& b) {
    asm("mov.b64 {%0, %1}, %2;" : "=f"(a), "=f"(b) : "l"(v));
}
__device__ __forceinline__ void ffma2(unsigned long long& d, unsigned long long a, unsigned long long b) {
    asm("fma.rn.f32x2 %0, %1, %2, %0;" : "+l"(d) : "l"(a), "l"(b));
}
__device__ __forceinline__ float ex2(float x) {
    float r;
    asm("ex2.approx.f32 %0, %1;" : "=f"(r) : "f"(x));
    return r;
}
__device__ __forceinline__ void cp16(unsigned int s, const void* g) {
    asm volatile("cp.async.cg.shared.global [%0], [%1], 16;" :: "r"(s), "l"(g));
}
#define CP_COMMIT() asm volatile("cp.async.commit_group;")
#define CP_WAIT1()  asm volatile("cp.async.wait_group 1;" ::: "memory")
#define CP_WAIT0()  asm volatile("cp.async.wait_group 0;" ::: "memory")

// ---------------- launch 1: hist + colsrc fill + housekeeping ----------------
__global__ void k_hist(const int* __restrict__ ei, int E) {
    int t = threadIdx.x;
    int gt = blockIdx.x * blockDim.x + t;
    if (blockIdx.x == 0) {
        if (t < 128) g_pub[t] = 0ull;
        if (t >= 128 && t < 160) {           // zero dummy rows
            g_rowA[NN * 32 + (t - 128)] = 0.f;
            g_rowB[NN * 32 + (t - 128)] = 0.f;
        }
    }
    // fill colsrc with dummy id NN
    int4 fv = make_int4(NN, NN, NN, NN);
    int4* c4 = (int4*)g_colsrc;
    for (int i = gt; i < NCOL / 4; i += gridDim.x * blockDim.x) c4[i] = fv;

    int E4 = E >> 2;
    const int4* d4p = (const int4*)(ei + E);
    if (gt < E4) {
        int4 d = __ldg(d4p + gt);
        atomicAdd(&g_counts[d.x], 1);
        atomicAdd(&g_counts[d.y], 1);
        atomicAdd(&g_counts[d.z], 1);
        atomicAdd(&g_counts[d.w], 1);
    }
    if (gt == 0) {
        for (int e = E4 * 4; e < E; e++) atomicAdd(&g_counts[ei[E + e]], 1);
    }
}

// ---------------- launch 2: single-pass scan over PADDED counts ----------------
__global__ void __launch_bounds__(1024) k_scan(int n) {
    int b = blockIdx.x, t = threadIdx.x, lane = t & 31, w = t >> 5;
    __shared__ int wsum[32];
    __shared__ int s_boff;

    int i = b * 1024 + t;
    int v = (i < n) ? g_counts[i] : 0;
    if (i < n) { g_counts[i] = 0; g_cnt[i] = v; }
    int vp = (v + 7) & ~7;                   // pad to multiple of 8

    int x = vp;
#pragma unroll
    for (int off = 1; off < 32; off <<= 1) {
        int y = __shfl_up_sync(0xffffffffu, x, off);
        if (lane >= off) x += y;
    }
    if (lane == 31) wsum[w] = x;
    __syncthreads();

    if (w == 0) {
        int y = wsum[lane];
        int inc = y;
#pragma unroll
        for (int off = 1; off < 32; off <<= 1) {
            int z = __shfl_up_sync(0xffffffffu, inc, off);
            if (lane >= off) inc += z;
        }
        int agg = __shfl_sync(0xffffffffu, inc, 31);
        wsum[lane] = inc - y;
        if (lane == 0) {
            if (b == 0) atomicExch(&g_pub[0], (2ull << 32) | (unsigned)agg);
            else        atomicExch(&g_pub[b], (1ull << 32) | (unsigned)agg);
        }
        if (b > 0) {
            long long run = 0;
            int base_j = b - 1;
            while (true) {
                int j = base_j - lane;
                unsigned long long p = 0ull;
                if (j >= 0) {
                    do { p = atomicAdd(&g_pub[j], 0ull); } while ((unsigned)(p >> 32) == 0u);
                }
                unsigned st = (j >= 0) ? (unsigned)(p >> 32) : 1u;
                unsigned val = (j >= 0) ? (unsigned)p : 0u;
                unsigned pmask = __ballot_sync(0xffffffffu, st == 2u);
                unsigned contrib;
                bool done;
                if (pmask) {
                    int firstP = __ffs(pmask) - 1;
                    contrib = (lane <= firstP) ? val : 0u;
                    done = true;
                } else {
                    contrib = val;
                    done = false;
                }
#pragma unroll
                for (int off = 16; off > 0; off >>= 1)
                    contrib += __shfl_xor_sync(0xffffffffu, contrib, off);
                run += contrib;
                if (done) break;
                base_j -= 32;
            }
            if (lane == 0) {
                atomicExch(&g_pub[b], (2ull << 32) | (unsigned)(run + agg));
                s_boff = (int)run;
            }
        } else if (lane == 0) {
            s_boff = 0;
        }
    }
    __syncthreads();

    int excl = s_boff + wsum[w] + (x - vp);
    if (i <= n) {
        g_rowptr[i] = excl;
        if (i < n) g_cursor[i] = excl;
    }
}

// ---------------- launch 3: fused gemm1 (cp.async) + scatter ----------------
#define TILE_STRIDE 20
#define TILE_FLOATS (256 * TILE_STRIDE)
#define G1_SMEM_BYTES ((FIN * HID + 2 * TILE_FLOATS) * 4)

__global__ void __launch_bounds__(256) k_fused(const float4* __restrict__ x4,
                                               const float* __restrict__ W1,
                                               const float* __restrict__ b1,
                                               const int* __restrict__ ei,
                                               int E, int n, int GB) {
    int t = threadIdx.x;
    if ((int)blockIdx.x >= GB) {
        int tt = (blockIdx.x - GB) * 256 + t;
        int E4 = E >> 2;
        const int4* s4p = (const int4*)ei;
        const int4* d4p = (const int4*)(ei + E);
        if (tt < E4) {
            int4 s = __ldg(s4p + tt);
            int4 d = __ldg(d4p + tt);
            int p;
            p = atomicAdd(&g_cursor[d.x], 1); g_colsrc[p] = s.x;
            p = atomicAdd(&g_cursor[d.y], 1); g_colsrc[p] = s.y;
            p = atomicAdd(&g_cursor[d.z], 1); g_colsrc[p] = s.z;
            p = atomicAdd(&g_cursor[d.w], 1); g_colsrc[p] = s.w;
        }
        if ((int)blockIdx.x == GB && t == 0) {
            for (int e = E4 * 4; e < E; e++) {
                int p = atomicAdd(&g_cursor[ei[E + e]], 1);
                g_colsrc[p] = ei[e];
            }
        }
        return;
    }

    extern __shared__ float dsm[];
    float* sW = dsm;
    float* tiles = dsm + FIN * HID;
    unsigned int sW_u = (unsigned int)__cvta_generic_to_shared(sW);
    unsigned int tiles_u = (unsigned int)__cvta_generic_to_shared(tiles);
    int row0 = blockIdx.x * 256;

    const float4* w4g = (const float4*)W1;
#pragma unroll
    for (int i = 0; i < 8; i++)
        cp16(sW_u + (i * 256 + t) * 16, &w4g[i * 256 + t]);
#pragma unroll
    for (int q = 0; q < 4; q++) {
        int id = q * 256 + t, r = id >> 2, c4 = id & 3;
        int gr = min(row0 + r, n - 1);
        cp16(tiles_u + (r * TILE_STRIDE + c4 * 4) * 4, &x4[(long)gr * (FIN / 4) + c4]);
    }
    CP_COMMIT();
#pragma unroll
    for (int q = 0; q < 4; q++) {
        int id = q * 256 + t, r = id >> 2, c4 = id & 3;
        int gr = min(row0 + r, n - 1);
        cp16(tiles_u + (TILE_FLOATS + r * TILE_STRIDE + c4 * 4) * 4, &x4[(long)gr * (FIN / 4) + 4 + c4]);
    }
    CP_COMMIT();

    unsigned long long acc[8];
#pragma unroll
    for (int j = 0; j < 8; j++) acc[j] = pk2(__ldg(&b1[2 * j]), __ldg(&b1[2 * j + 1]));

#pragma unroll 1
    for (int kt = 0; kt < 32; kt++) {
        if (kt == 31) { CP_WAIT0(); } else { CP_WAIT1(); }
        __syncthreads();
        float* tile = tiles + (kt & 1) * TILE_FLOATS;
#pragma unroll
        for (int c4 = 0; c4 < 4; c4++) {
            float4 xv = *(const float4*)&tile[t * TILE_STRIDE + c4 * 4];
#pragma unroll
            for (int c = 0; c < 4; c++) {
                float xs = (c == 0) ? xv.x : (c == 1) ? xv.y : (c == 2) ? xv.z : xv.w;
                unsigned long long xx = pk2(xs, xs);
                const ulonglong2* w = (const ulonglong2*)&sW[(kt * 16 + c4 * 4 + c) * HID];
                ulonglong2 wa = w[0], wb = w[1], wc = w[2], wd = w[3];
                ffma2(acc[0], xx, wa.x); ffma2(acc[1], xx, wa.y);
                ffma2(acc[2], xx, wb.x); ffma2(acc[3], xx, wb.y);
                ffma2(acc[4], xx, wc.x); ffma2(acc[5], xx, wc.y);
                ffma2(acc[6], xx, wd.x); ffma2(acc[7], xx, wd.y);
            }
        }
        __syncthreads();
        if (kt + 2 < 32) {
#pragma unroll
            for (int q = 0; q < 4; q++) {
                int id = q * 256 + t, r = id >> 2, c4 = id & 3;
                int gr = min(row0 + r, n - 1);
                cp16(tiles_u + ((kt & 1) * TILE_FLOATS + r * TILE_STRIDE + c4 * 4) * 4,
                     &x4[(long)gr * (FIN / 4) + (kt + 2) * 4 + c4]);
            }
            CP_COMMIT();
        }
    }

    int row = row0 + t;
    if (row >= n) return;
    float o[16];
    float ss = 0.f;
#pragma unroll
    for (int j = 0; j < 8; j++) {
        float a, b;
        upk2(acc[j], a, b);
        a = fmaxf(a, 0.f);
        b = fmaxf(b, 0.f);
        o[2 * j] = a; o[2 * j + 1] = b;
        ss += a * a + b * b;
    }
    float inv = 1.0f / fmaxf(sqrtf(ss), 1e-12f);
    float4* r4 = (float4*)&g_rowA[(long)row * 32];
#pragma unroll
    for (int j = 0; j < 4; j++) {
        float4 raw = make_float4(o[4 * j], o[4 * j + 1], o[4 * j + 2], o[4 * j + 3]);
        r4[j] = scl4(raw, inv);
        r4[4 + j] = raw;
    }
}

// ---------------- launches 4,5: AGNN layer — branch-free padded loop ----------------
// Rows padded to multiples of 8 with dummy node NN (zero row): pad edges give
// cos=0 -> p=1, aggregate 0; corrected by s -= npad (exact). No validity logic.
__global__ void __launch_bounds__(256) k_agnn(const float* __restrict__ beta_p,
                                              const float4* __restrict__ rowIn,
                                              float4* __restrict__ rowOut,
                                              int outMode, int n) {
    int lane = threadIdx.x & 31;
    int warp = threadIdx.x >> 5;
    int node = blockIdx.x * 8 + warp;
    if (node >= n) return;
    int sub = lane & 7;
    int slot = lane >> 3;
    bool hi = sub >= 4;                  // raw half
    float b2 = __ldg(beta_p) * 1.4426950408889634f;   // fold log2(e)

    float4 dv = rowIn[(long)node * 8 + sub];

    float cs = hi ? 0.f : d4(dv, dv);
    cs += __shfl_xor_sync(0xffffffffu, cs, 1, 8);
    cs += __shfl_xor_sync(0xffffffffu, cs, 2, 8);
    cs += __shfl_xor_sync(0xffffffffu, cs, 4, 8);

    int e0 = g_rowptr[node];
    int cntP = g_rowptr[node + 1] - e0;              // multiple of 8
    int npad = cntP - g_cnt[node];
    const int* cp = g_colsrc + e0 + slot;

    float s = 0.f;
    float4 a = make_float4(0.f, 0.f, 0.f, 0.f);

    // pipeline prologue (reads stay within padded+slack region; ids always valid)
    int cA0 = __ldg(cp + 0), cB0 = __ldg(cp + 4);
    float4 rA0 = __ldg(&rowIn[(long)cA0 * 8 + sub]);
    float4 rB0 = __ldg(&rowIn[(long)cB0 * 8 + sub]);
    int cA1 = __ldg(cp + 8), cB1 = __ldg(cp + 12);

#pragma unroll 2
    for (int base = 0; base < cntP; base += 8) {
        int cA2 = __ldg(cp + base + 16);
        int cB2 = __ldg(cp + base + 20);
        float4 rA1 = __ldg(&rowIn[(long)cA1 * 8 + sub]);
        float4 rB1 = __ldg(&rowIn[(long)cB1 * 8 + sub]);

        float pA = hi ? 0.f : d4(dv, rA0);
        float pB = hi ? 0.f : d4(dv, rB0);
        pA += __shfl_xor_sync(0xffffffffu, pA, 1, 8);
        pB += __shfl_xor_sync(0xffffffffu, pB, 1, 8);
        pA += __shfl_xor_sync(0xffffffffu, pA, 2, 8);
        pB += __shfl_xor_sync(0xffffffffu, pB, 2, 8);
        pA += __shfl_xor_sync(0xffffffffu, pA, 4, 8);
        pB += __shfl_xor_sync(0xffffffffu, pB, 4, 8);
        float eA = ex2(b2 * pA);
        float eB = ex2(b2 * pB);
        s += eA + eB;
        a.x += eA * rA0.x + eB * rB0.x;
        a.y += eA * rA0.y + eB * rB0.y;
        a.z += eA * rA0.z + eB * rB0.z;
        a.w += eA * rA0.w + eB * rB0.w;

        rA0 = rA1; rB0 = rB1;
        cA1 = cA2; cB1 = cB2;
    }

    // combine the 4 slot partials
#pragma unroll
    for (int off = 8; off <= 16; off <<= 1) {
        s += __shfl_xor_sync(0xffffffffu, s, off);
        a.x += __shfl_xor_sync(0xffffffffu, a.x, off);
        a.y += __shfl_xor_sync(0xffffffffu, a.y, off);
        a.z += __shfl_xor_sync(0xffffffffu, a.z, off);
        a.w += __shfl_xor_sync(0xffffffffu, a.w, off);
    }

    s -= (float)npad;                 // pads contributed exactly 1.0 each

    // implicit self-loop
    float ps = ex2(b2 * cs);
    s += ps;
    a.x += ps * dv.x; a.y += ps * dv.y; a.z += ps * dv.z; a.w += ps * dv.w;

    if (hi) {
        float inv = 1.0f / s;
        float4 o = scl4(a, inv);
        if (outMode == 0) {
            float ss2 = d4(o, o);
            ss2 += __shfl_xor_sync(0xffffffffu, ss2, 1, 8);
            ss2 += __shfl_xor_sync(0xffffffffu, ss2, 2, 8);
            float invn = 1.0f / fmaxf(sqrtf(ss2), 1e-12f);
            rowOut[(long)node * 8 + (sub - 4)] = scl4(o, invn);
            rowOut[(long)node * 8 + sub] = o;
        } else {
            float4* out4 = (float4*)g_bufA;
            out4[(long)node * 4 + (sub - 4)] = o;
        }
    }
}

// ---------------- launch 6: out = log_softmax(h @ W2 + b2) ----------------
__global__ void k_gemm2(const float* __restrict__ W2, const float* __restrict__ b2,
                        float* __restrict__ out, int n) {
    __shared__ float sW[HID * NC];
    __shared__ float sB[NC];
    for (int i = threadIdx.x; i < HID * NC; i += blockDim.x) sW[i] = __ldg(&W2[i]);
    if (threadIdx.x < NC) sB[threadIdx.x] = __ldg(&b2[threadIdx.x]);
    __syncthreads();

    int warp = threadIdx.x >> 5, lane = threadIdx.x & 31;
    int row = blockIdx.x * (blockDim.x >> 5) + warp;
    if (row >= n) return;

    const float* h = g_bufA;
    float hv = (lane < HID) ? h[(long)row * HID + lane] : 0.f;
    float z0 = sB[lane], z1 = sB[lane + 32];
#pragma unroll
    for (int k = 0; k < HID; k++) {
        float hk = __shfl_sync(0xffffffffu, hv, k);
        z0 += hk * sW[k * NC + lane];
        z1 += hk * sW[k * NC + 32 + lane];
    }
    float mx = fmaxf(z0, z1);
#pragma unroll
    for (int off = 16; off > 0; off >>= 1) mx = fmaxf(mx, __shfl_xor_sync(0xffffffffu, mx, off));
    float p = __expf(z0 - mx) + __expf(z1 - mx);
#pragma unroll
    for (int off = 16; off > 0; off >>= 1) p += __shfl_xor_sync(0xffffffffu, p, off);
    float lse = mx + __logf(p);
    out[(long)row * NC + lane] = z0 - lse;
    out[(long)row * NC + 32 + lane] = z1 - lse;
}

// ---------------- launch ----------------
extern "C" void kernel_launch(void* const* d_in, const int* in_sizes, int n_in,
                              void* d_out, int out_size) {
    const float* x = (const float*)d_in[0];
    const int* ei = (const int*)d_in[1];
    const float* W1 = (const float*)d_in[2];
    const float* b1 = (const float*)d_in[3];
    const float* W2 = (const float*)d_in[4];
    const float* b2 = (const float*)d_in[5];
    const float* beta1 = (const float*)d_in[6];
    const float* beta2 = (const float*)d_in[7];
    float* out = (float*)d_out;

    int N = in_sizes[0] / FIN;
    int E = in_sizes[1] / 2;

    static int smemSet = 0;
    if (!smemSet) {
        cudaFuncSetAttribute(k_fused, cudaFuncAttributeMaxDynamicSharedMemorySize, G1_SMEM_BYTES);
        smemSet = 1;
    }

    float4* rowA4 = nullptr;
    float4* rowB4 = nullptr;
    cudaGetSymbolAddress((void**)&rowA4, g_rowA);
    cudaGetSymbolAddress((void**)&rowB4, g_rowB);

    int NBscan = (N + 1 + 1023) / 1024;
    int GB = (N + 255) / 256;
    int SB = (E / 4 + 255) / 256;

    // 1: hist (+ colsrc dummy fill, pub zero, dummy rows zero)
    k_hist<<<SB, 256>>>(ei, E);
    // 2: single-pass padded scan (re-zeroes counts, stores real degrees)
    k_scan<<<NBscan, 1024>>>(N);
    // 3: fused gemm1 + scatter
    k_fused<<<GB + SB, 256, G1_SMEM_BYTES>>>((const float4*)x, W1, b1, ei, E, N, GB);
    // 4: agnn layer 1 (PROFILED)  rowA -> rowB
    k_agnn<<<(N + 7) / 8, 256>>>(beta1, rowA4, rowB4, 0, N);
    // 5: agnn layer 2  rowB -> bufA
    k_agnn<<<(N + 7) / 8, 256>>>(beta2, rowB4, nullptr, 1, N);
    // 6: MLP out + log_softmax
    k_gemm2<<<(N + 7) / 8, 256>>>(W2, b2, out, N);
}